// round 9
// baseline (speedup 1.0000x reference)
#include <cuda_runtime.h>
#include <cuda_bf16.h>
#include <stdint.h>
#include <math.h>

#define NB 8
#define NL 4096

// ================= scratch (device globals) =================
__device__ __align__(1024) __nv_bfloat16 g_xT_hi[(size_t)NB * NL * 512];
__device__ __align__(1024) __nv_bfloat16 g_xT_lo[(size_t)NB * NL * 512];
__device__ __align__(1024) __nv_bfloat16 g_catT_hi[(size_t)NB * NL * 1024];
__device__ __align__(1024) __nv_bfloat16 g_catT_lo[(size_t)NB * NL * 1024];
__device__ __align__(1024) __nv_bfloat16 g_tmpT_hi[(size_t)NB * NL * 256];
__device__ __align__(1024) __nv_bfloat16 g_tmpT_lo[(size_t)NB * NL * 256];
__device__ __align__(1024) __nv_bfloat16 g_sdT_hi[(size_t)NB * NL * 256];
__device__ __align__(1024) __nv_bfloat16 g_sdT_lo[(size_t)NB * NL * 256];
__device__ __align__(1024) float g_P[(size_t)NB * NL * 384];   // 256 val | 64 off | 32 aw | 32 pad
__device__ float g_bias384[384];
__device__ float g_biasF[512];                                  // folded cv2 bias

// Pre-swizzled weight tiles: [n_tile][stage][ hi 16KB | lo 16KB ]
// tile: 128 co rows x 64 bf16 K; row r at r*128 + (kbyte ^ ((r&7)*16))  (ldmatrix-ready)
__device__ __align__(1024) uint8_t g_Wcv1 [4  * 8  * 32768];   // 512 co, K=512
__device__ __align__(1024) uint8_t g_Wc   [4][2 * 36 * 32768]; // 256 co, K=2304 (9 taps x 256 ci)
__device__ __align__(1024) uint8_t g_Wproj[3  * 4  * 32768];   // 384 co (padded), K=256
__device__ __align__(1024) uint8_t g_Wcv2 [4  * 20 * 32768];   // 512 co, K=1280 (last 256 = folded out_w)

__device__ __forceinline__ float silu_f(float x) { return x / (1.0f + expf(-x)); }

// ================= PTX helpers (compute_103-safe) =================
__device__ __forceinline__ uint32_t smem_u32(const void* p) {
    uint32_t a;
    asm("{ .reg .u64 t; cvta.to.shared.u64 t, %1; cvt.u32.u64 %0, t; }" : "=r"(a) : "l"(p));
    return a;
}
#define CP_COMMIT() asm volatile("cp.async.commit_group;" ::: "memory")
#define CP_WAIT(n)  asm volatile("cp.async.wait_group %0;" :: "n"(n) : "memory")

__device__ __forceinline__ void cpa16(uint32_t d, const void* s, int sz) {
    asm volatile("cp.async.cg.shared.global [%0], [%1], 16, %2;"
                 :: "r"(d), "l"(s), "r"(sz) : "memory");
}
__device__ __forceinline__ void ldsm4(uint32_t a, uint32_t* r) {
    asm volatile("ldmatrix.sync.aligned.m8n8.x4.shared.b16 {%0,%1,%2,%3}, [%4];"
                 : "=r"(r[0]), "=r"(r[1]), "=r"(r[2]), "=r"(r[3]) : "r"(a));
}
__device__ __forceinline__ void mma16816(float* d, const uint32_t* a, const uint32_t* b) {
    asm volatile("mma.sync.aligned.m16n8k16.row.col.f32.bf16.bf16.f32 "
                 "{%0,%1,%2,%3}, {%4,%5,%6,%7}, {%8,%9}, {%0,%1,%2,%3};"
                 : "+f"(d[0]), "+f"(d[1]), "+f"(d[2]), "+f"(d[3])
                 : "r"(a[0]), "r"(a[1]), "r"(a[2]), "r"(a[3]), "r"(b[0]), "r"(b[1]));
}

// ================= weight prep =================
__device__ __forceinline__ void wstore(uint8_t* dst, int n_stages, int co, int k, float v) {
    int tile = co >> 7, rr = co & 127, st = k >> 6, kk = k & 63;
    __nv_bfloat16 h = __float2bfloat16(v);
    __nv_bfloat16 l = __float2bfloat16(v - __bfloat162float(h));
    size_t base = (size_t)(tile * n_stages + st) * 32768;
    uint32_t off = (uint32_t)(rr * 128 + ((kk * 2) ^ ((rr & 7) * 16)));
    *(__nv_bfloat16*)(dst + base + off) = h;
    *(__nv_bfloat16*)(dst + base + 16384 + off) = l;
}

__global__ void prep_cv1(const float* __restrict__ w) {
    int i = blockIdx.x * 256 + threadIdx.x;            // 512*512
    int co = i >> 9, k = i & 511;
    wstore(g_Wcv1, 8, co, k, w[co * 512 + k]);
}
__global__ void prep_conv(const float* __restrict__ w, uint8_t* __restrict__ dst) {
    int i = blockIdx.x * 256 + threadIdx.x;            // 256*2304
    int co = i / 2304, k = i - co * 2304;
    int tap = k >> 8, ci = k & 255;
    wstore(dst, 36, co, k, w[(co * 256 + ci) * 9 + tap]);
}
__global__ void prep_proj(const float* __restrict__ vw, const float* __restrict__ ow,
                          const float* __restrict__ aww) {
    int i = blockIdx.x * 256 + threadIdx.x;            // 384*256
    int co = i >> 8, k = i & 255;
    float v = (co < 256) ? vw[k * 256 + co]
            : (co < 320) ? ow[k * 64 + (co - 256)]
            : (co < 352) ? aww[k * 32 + (co - 320)] : 0.f;
    wstore(g_Wproj, 4, co, k, v);
}
__global__ void prep_bias(const float* __restrict__ vb, const float* __restrict__ ob,
                          const float* __restrict__ awb) {
    int j = blockIdx.x * 128 + threadIdx.x;
    if (j < 384)
        g_bias384[j] = (j < 256) ? vb[j] : (j < 320) ? ob[j - 256] : (j < 352) ? awb[j - 320] : 0.f;
}
__global__ void prep_cv2(const float* __restrict__ w) {
    int i = blockIdx.x * 256 + threadIdx.x;            // 512*1024 (first 16 stages)
    int co = i >> 10, k = i & 1023;
    wstore(g_Wcv2, 20, co, k, w[co * 1280 + k]);
}
// Fold out-projection into cv2: Wfold[o][d] = sum_c cv2_w[o][1024+c] * out_w[d][c]
__global__ void prep_fold(const float* __restrict__ cv2w, const float* __restrict__ outw) {
    __shared__ float srow[256];
    int o = blockIdx.x, d = threadIdx.x;
    srow[d] = cv2w[o * 1280 + 1024 + d];
    __syncthreads();
    float acc = 0.f;
#pragma unroll 8
    for (int c = 0; c < 256; c++) acc = fmaf(srow[c], outw[d * 256 + c], acc);
    wstore(g_Wcv2, 20, o, 1024 + d, acc);
}
__global__ void prep_foldb(const float* __restrict__ cv2w, const float* __restrict__ outb) {
    int o = blockIdx.x * 256 + threadIdx.x;            // 512
    float acc = 0.f;
    for (int c = 0; c < 256; c++) acc = fmaf(cv2w[o * 1280 + 1024 + c], outb[c], acc);
    g_biasF[o] = acc;
}

// ================= x -> xT hi/lo =================
__global__ void xT_kernel(const float* __restrict__ x) {
    __shared__ float t[32][33];
    int b = blockIdx.z;
    int p0 = blockIdx.x * 32, c0 = blockIdx.y * 32;
    int tx = threadIdx.x, ty = threadIdx.y;            // (32, 8)
    const float* xb = x + (size_t)b * 512 * 4096;
#pragma unroll
    for (int i = 0; i < 4; i++)
        t[ty + i * 8][tx] = xb[(size_t)(c0 + ty + i * 8) * 4096 + p0 + tx];
    __syncthreads();
#pragma unroll
    for (int i = 0; i < 4; i++) {
        int pp = p0 + ty + i * 8, cc = c0 + tx;
        float v = t[tx][ty + i * 8];
        __nv_bfloat16 h = __float2bfloat16(v);
        __nv_bfloat16 l = __float2bfloat16(v - __bfloat162float(h));
        size_t idx = ((size_t)b * 4096 + pp) * 512 + cc;
        g_xT_hi[idx] = h;
        g_xT_lo[idx] = l;
    }
}

// ================= tensor-core GEMM (mma.sync bf16, split hi/lo x3) =================
// R7-proven config: double buffer, per-accumulator interleaved MMA order.
// Stages >= splitS read from A2 (second activation tensor) — feeds cv2 from sdT.
__global__ void __launch_bounds__(256, 1)
gemm_tc(const __nv_bfloat16* __restrict__ A_hi, const __nv_bfloat16* __restrict__ A_lo,
        int Cs, int c0,
        const __nv_bfloat16* __restrict__ A2_hi, const __nv_bfloat16* __restrict__ A2_lo,
        int Cs2, int splitS,
        const uint8_t* __restrict__ W, int n_stages, int conv_mode,
        float* __restrict__ outF,
        __nv_bfloat16* __restrict__ O_hi, __nv_bfloat16* __restrict__ O_lo,
        int CsO, int c0O,
        const float* __restrict__ bias, int out_mode, int act)
{
    extern __shared__ uint8_t dyn[];
    uint8_t* dynp = dyn + ((1024u - (smem_u32(dyn) & 1023u)) & 1023u);
    uint32_t dynb = smem_u32(dynp);

    int tid = threadIdx.x;
    int lane = tid & 31, w = tid >> 5;
    int b = blockIdx.z, n_tile = blockIdx.x;
    int p0 = blockIdx.y * 128;

    const __nv_bfloat16* Ah = A_hi + (size_t)b * NL * Cs + c0;
    const __nv_bfloat16* Al = A_lo + (size_t)b * NL * Cs + c0;
    const __nv_bfloat16* A2h = A2_hi ? A2_hi + (size_t)b * NL * Cs2 : nullptr;
    const __nv_bfloat16* A2l = A2_lo ? A2_lo + (size_t)b * NL * Cs2 : nullptr;
    const uint8_t* Wt = W + (size_t)n_tile * n_stages * 32768;

    // ---- cp.async stage loader (double buffer) ----
    auto issue = [&](int s, int buf) {
        uint32_t bo = dynb + buf * 65536;
        const __nv_bfloat16 *ah, *al;
        int cs, ci0, ky = 0, kx = 0;
        if (s >= splitS) {
            ah = A2h; al = A2l; cs = Cs2; ci0 = (s - splitS) * 64;
        } else if (conv_mode) {
            int tap = s >> 2; ky = tap / 3; kx = tap - ky * 3;
            ah = Ah; al = Al; cs = Cs; ci0 = (s & 3) * 64;
        } else {
            ah = Ah; al = Al; cs = Cs; ci0 = s * 64;
        }
#pragma unroll
        for (int t = 0; t < 4; t++) {
            int f = tid + t * 256;                    // 0..1023
            int row = f >> 3, q = f & 7;
            int p = p0 + row;
            int psrc = p, valid = 1;
            if (conv_mode && s < splitS) {
                int yy = (p >> 6) + ky - 1, xx = (p & 63) + kx - 1;
                valid = ((unsigned)yy < 64u) && ((unsigned)xx < 64u);
                psrc = valid ? (p + (ky - 1) * 64 + (kx - 1)) : p;
            }
            uint32_t off = (uint32_t)(row * 128 + ((q * 16) ^ ((row & 7) * 16)));
            int sz = valid ? 16 : 0;
            cpa16(bo + off,         ah + (size_t)psrc * cs + ci0 + q * 8, sz);
            cpa16(bo + 16384 + off, al + (size_t)psrc * cs + ci0 + q * 8, sz);
        }
        const uint8_t* ws = Wt + (size_t)s * 32768;
#pragma unroll
        for (int t = 0; t < 8; t++) {
            int f = tid + t * 256;                    // 0..2047 -> 32KB (hi+lo)
            cpa16(bo + 32768 + f * 16, ws + f * 16, 16);
        }
    };

    // ---- per-lane ldmatrix bases ----
    int lr = lane & 7, g = lane >> 3;
    int m0w = (w & 3) * 32, n0w = (w >> 2) * 64;
    uint32_t xorv = (uint32_t)(lr * 16);
    int kfixA = (g >> 1) * 16;
    int rowA = m0w + (g & 1) * 8 + lr;
    uint32_t aBase[2];
    aBase[0] = dynb + (uint32_t)(rowA * 128);
    aBase[1] = dynb + (uint32_t)((rowA + 16) * 128);
    int kfixB = (g & 1) * 16;
    uint32_t bBase[4];
#pragma unroll
    for (int bp = 0; bp < 4; bp++) {
        int rowB = n0w + bp * 16 + (g >> 1) * 8 + lr;
        bBase[bp] = dynb + 32768u + (uint32_t)(rowB * 128);
    }

    float acc[2][8][4];
#pragma unroll
    for (int mi = 0; mi < 2; mi++)
#pragma unroll
        for (int ng = 0; ng < 8; ng++)
#pragma unroll
            for (int q = 0; q < 4; q++) acc[mi][ng][q] = 0.f;

    issue(0, 0); CP_COMMIT();

    for (int s = 0; s < n_stages; s++) {
        int buf = s & 1;
        if (s + 1 < n_stages) { issue(s + 1, buf ^ 1); CP_COMMIT(); CP_WAIT(1); }
        else                  { CP_WAIT(0); }
        __syncthreads();

        uint32_t bo = (uint32_t)(buf * 65536);
#pragma unroll
        for (int kk8 = 0; kk8 < 4; kk8++) {
            int kb = kk8 * 32;
            uint32_t ka  = (uint32_t)((kb + kfixA) ^ (int)xorv);
            uint32_t kbb = (uint32_t)((kb + kfixB) ^ (int)xorv);
            uint32_t ahf[2][4], alf[2][4];
            ldsm4(aBase[0] + bo + ka,          ahf[0]);
            ldsm4(aBase[1] + bo + ka,          ahf[1]);
            ldsm4(aBase[0] + 16384 + bo + ka,  alf[0]);
            ldsm4(aBase[1] + 16384 + bo + ka,  alf[1]);
            uint32_t bhf[4][4], blf[4][4];
#pragma unroll
            for (int bp = 0; bp < 4; bp++) {
                ldsm4(bBase[bp] + bo + kbb,         bhf[bp]);
                ldsm4(bBase[bp] + 16384 + bo + kbb, blf[bp]);
            }
#pragma unroll
            for (int mi = 0; mi < 2; mi++)
#pragma unroll
                for (int ng = 0; ng < 8; ng++) {
                    const uint32_t* bh = &bhf[ng >> 1][(ng & 1) * 2];
                    const uint32_t* bl = &blf[ng >> 1][(ng & 1) * 2];
                    mma16816(acc[mi][ng], ahf[mi], bh);   // hi*hi
                    mma16816(acc[mi][ng], ahf[mi], bl);   // hi*lo
                    mma16816(acc[mi][ng], alf[mi], bh);   // lo*hi
                }
        }
        __syncthreads();
    }

    // ---- epilogue ----
    int prb = p0 + m0w + (lane >> 2);
    int colb = n0w + 2 * (lane & 3);
#pragma unroll
    for (int mi = 0; mi < 2; mi++)
#pragma unroll
        for (int ng = 0; ng < 8; ng++) {
            int cog = n_tile * 128 + colb + ng * 8;
#pragma unroll
            for (int half = 0; half < 2; half++) {
                int pe = prb + mi * 16 + half * 8;
                float v0 = acc[mi][ng][half * 2 + 0];
                float v1 = acc[mi][ng][half * 2 + 1];
                if (out_mode == 0) {
                    if (bias) { v0 += bias[cog]; v1 += bias[cog + 1]; }
                    if (act)  { v0 = silu_f(v0); v1 = silu_f(v1); }
                    __nv_bfloat16 h0 = __float2bfloat16(v0), h1 = __float2bfloat16(v1);
                    __nv_bfloat16 l0 = __float2bfloat16(v0 - __bfloat162float(h0));
                    __nv_bfloat16 l1 = __float2bfloat16(v1 - __bfloat162float(h1));
                    uint32_t hp = (uint32_t)__bfloat16_as_ushort(h0) | ((uint32_t)__bfloat16_as_ushort(h1) << 16);
                    uint32_t lp = (uint32_t)__bfloat16_as_ushort(l0) | ((uint32_t)__bfloat16_as_ushort(l1) << 16);
                    size_t ob = ((size_t)b * NL + pe) * CsO + c0O + cog;
                    *(uint32_t*)(O_hi + ob) = hp;
                    *(uint32_t*)(O_lo + ob) = lp;
                } else if (out_mode == 1) {
                    float2 v;
                    v.x = v0 + bias[cog];
                    v.y = v1 + bias[cog + 1];
                    *(float2*)&outF[((size_t)b * NL + pe) * 384 + cog] = v;
                } else {
                    float b0 = bias ? bias[cog] : 0.f;
                    float b1 = bias ? bias[cog + 1] : 0.f;
                    outF[((size_t)(b * 512 + cog)     << 12) + pe] = silu_f(v0 + b0);
                    outF[((size_t)(b * 512 + cog + 1) << 12) + pe] = silu_f(v1 + b1);
                }
            }
        }
}

// ================= deformable sampling =================
__global__ void msda_kernel(const float* __restrict__ P, const float* __restrict__ rb)
{
    int warp = threadIdx.x >> 5;
    int lane = threadIdx.x & 31;
    long long gw = (long long)blockIdx.x * 8 + warp;
    int h = (int)(gw & 7);
    long long bl = gw >> 3;
    long long b = bl >> 12;
    const float* Pl = P + bl * 384;
    const float* Vb = P + b * (long long)NL * 384;
    float rbx = rb[bl * 2 + 0];
    float rby = rb[bl * 2 + 1];

    float lg[4];
    float mx = -1e30f;
#pragma unroll
    for (int pp = 0; pp < 4; pp++) { lg[pp] = Pl[320 + h * 4 + pp]; mx = fmaxf(mx, lg[pp]); }
    float s = 0.f;
#pragma unroll
    for (int pp = 0; pp < 4; pp++) { lg[pp] = expf(lg[pp] - mx); s += lg[pp]; }
    float inv = 1.f / s;

    int hoff = h * 32 + lane;
    float acc = 0.f;
#pragma unroll
    for (int pp = 0; pp < 4; pp++) {
        float ox = Pl[256 + h * 8 + pp * 2 + 0];
        float oy = Pl[256 + h * 8 + pp * 2 + 1];
        float gx = (rbx + ox * (1.f / 64.f)) * 64.f - 0.5f;
        float gy = (rby + oy * (1.f / 64.f)) * 64.f - 0.5f;
        float x0f = floorf(gx), y0f = floorf(gy);
        int x0 = (int)x0f, y0 = (int)y0f;
        float wx1 = gx - x0f, wy1 = gy - y0f;
        float wx0 = 1.f - wx1, wy0 = 1.f - wy1;

        float v00 = 0.f, v10 = 0.f, v01 = 0.f, v11 = 0.f;
        if ((unsigned)x0       < 64u && (unsigned)y0       < 64u) v00 = Vb[(long long)(y0 * 64 + x0) * 384 + hoff];
        if ((unsigned)(x0 + 1) < 64u && (unsigned)y0       < 64u) v10 = Vb[(long long)(y0 * 64 + x0 + 1) * 384 + hoff];
        if ((unsigned)x0       < 64u && (unsigned)(y0 + 1) < 64u) v01 = Vb[(long long)((y0 + 1) * 64 + x0) * 384 + hoff];
        if ((unsigned)(x0 + 1) < 64u && (unsigned)(y0 + 1) < 64u) v11 = Vb[(long long)((y0 + 1) * 64 + x0 + 1) * 384 + hoff];

        float sv = v00 * (wx0 * wy0) + v10 * (wx1 * wy0) + v01 * (wx0 * wy1) + v11 * (wx1 * wy1);
        acc = fmaf(lg[pp] * inv, sv, acc);
    }
    __nv_bfloat16 hv = __float2bfloat16(acc);
    __nv_bfloat16 lv = __float2bfloat16(acc - __bfloat162float(hv));
    size_t idx = (size_t)bl * 256 + hoff;
    g_sdT_hi[idx] = hv;
    g_sdT_lo[idx] = lv;
}

// ================= launch =================
extern "C" void kernel_launch(void* const* d_in, const int* in_sizes, int n_in,
                              void* d_out, int out_size)
{
    const float* x       = (const float*)d_in[0];
    const float* rb      = (const float*)d_in[1];
    const float* cv1_w   = (const float*)d_in[3];
    const float* m0c1    = (const float*)d_in[4];
    const float* m0c2    = (const float*)d_in[5];
    const float* m1c1    = (const float*)d_in[6];
    const float* m1c2    = (const float*)d_in[7];
    const float* vproj_w = (const float*)d_in[8];
    const float* vproj_b = (const float*)d_in[9];
    const float* off_w   = (const float*)d_in[10];
    const float* off_b   = (const float*)d_in[11];
    const float* aw_w    = (const float*)d_in[12];
    const float* aw_b    = (const float*)d_in[13];
    const float* out_w   = (const float*)d_in[14];
    const float* out_b   = (const float*)d_in[15];
    const float* cv2_w   = (const float*)d_in[16];
    float* out = (float*)d_out;

    __nv_bfloat16 *xT_h, *xT_l, *catT_h, *catT_l, *tmpT_h, *tmpT_l, *sdT_h, *sdT_l;
    float *P, *bias384, *biasF;
    uint8_t *Wcv1, *Wc, *Wproj, *Wcv2;
    cudaGetSymbolAddress((void**)&xT_h,   g_xT_hi);
    cudaGetSymbolAddress((void**)&xT_l,   g_xT_lo);
    cudaGetSymbolAddress((void**)&catT_h, g_catT_hi);
    cudaGetSymbolAddress((void**)&catT_l, g_catT_lo);
    cudaGetSymbolAddress((void**)&tmpT_h, g_tmpT_hi);
    cudaGetSymbolAddress((void**)&tmpT_l, g_tmpT_lo);
    cudaGetSymbolAddress((void**)&sdT_h,  g_sdT_hi);
    cudaGetSymbolAddress((void**)&sdT_l,  g_sdT_lo);
    cudaGetSymbolAddress((void**)&P,      g_P);
    cudaGetSymbolAddress((void**)&bias384,g_bias384);
    cudaGetSymbolAddress((void**)&biasF,  g_biasF);
    cudaGetSymbolAddress((void**)&Wcv1,   g_Wcv1);
    cudaGetSymbolAddress((void**)&Wc,     g_Wc);
    cudaGetSymbolAddress((void**)&Wproj,  g_Wproj);
    cudaGetSymbolAddress((void**)&Wcv2,   g_Wcv2);

    const int SMEM_DYN = 2 * 65536 + 1024;
    cudaFuncSetAttribute(gemm_tc, cudaFuncAttributeMaxDynamicSharedMemorySize, SMEM_DYN);

    const size_t WCS = 2ull * 36 * 32768;
    const int BIG = 1 << 30;

    // ---- prep ----
    prep_cv1 <<<1024, 256>>>(cv1_w);
    prep_conv<<<2304, 256>>>(m0c1, Wc + 0 * WCS);
    prep_conv<<<2304, 256>>>(m0c2, Wc + 1 * WCS);
    prep_conv<<<2304, 256>>>(m1c1, Wc + 2 * WCS);
    prep_conv<<<2304, 256>>>(m1c2, Wc + 3 * WCS);
    prep_proj<<<384, 256>>>(vproj_w, off_w, aw_w);
    prep_bias<<<3, 128>>>(vproj_b, off_b, aw_b);
    prep_cv2 <<<2048, 256>>>(cv2_w);
    prep_fold<<<512, 256>>>(cv2_w, out_w);
    prep_foldb<<<2, 256>>>(cv2_w, out_b);
    xT_kernel<<<dim3(128, 16, NB), dim3(32, 8)>>>(x);

    // ---- cv1: xT[512] -> catT[0:512) (SiLU) ----
    gemm_tc<<<dim3(4, 32, NB), 256, SMEM_DYN>>>(xT_h, xT_l, 512, 0,
        nullptr, nullptr, 0, BIG, Wcv1, 8, 0,
        nullptr, catT_h, catT_l, 1024, 0, nullptr, 0, 1);
    // ---- conv0: catT b[256:512) -> tmpT (SiLU) ----
    gemm_tc<<<dim3(2, 32, NB), 256, SMEM_DYN>>>(catT_h, catT_l, 1024, 256,
        nullptr, nullptr, 0, BIG, Wc + 0 * WCS, 36, 1,
        nullptr, tmpT_h, tmpT_l, 256, 0, nullptr, 0, 1);
    // ---- conv1: tmpT -> catT b1[512:768) (SiLU) ----
    gemm_tc<<<dim3(2, 32, NB), 256, SMEM_DYN>>>(tmpT_h, tmpT_l, 256, 0,
        nullptr, nullptr, 0, BIG, Wc + 1 * WCS, 36, 1,
        nullptr, catT_h, catT_l, 1024, 512, nullptr, 0, 1);
    // ---- conv2: catT b1 -> tmpT (SiLU) ----
    gemm_tc<<<dim3(2, 32, NB), 256, SMEM_DYN>>>(catT_h, catT_l, 1024, 512,
        nullptr, nullptr, 0, BIG, Wc + 2 * WCS, 36, 1,
        nullptr, tmpT_h, tmpT_l, 256, 0, nullptr, 0, 1);
    // ---- conv3: tmpT -> catT b2[768:1024) (SiLU) ----
    gemm_tc<<<dim3(2, 32, NB), 256, SMEM_DYN>>>(tmpT_h, tmpT_l, 256, 0,
        nullptr, nullptr, 0, BIG, Wc + 3 * WCS, 36, 1,
        nullptr, catT_h, catT_l, 1024, 768, nullptr, 0, 1);
    // ---- proj: catT b2 -> P[b][p][384] (+bias) ----
    gemm_tc<<<dim3(3, 32, NB), 256, SMEM_DYN>>>(catT_h, catT_l, 1024, 768,
        nullptr, nullptr, 0, BIG, Wproj, 4, 0,
        P, nullptr, nullptr, 0, 0, bias384, 1, 0);
    // ---- deformable sampling -> sdT hi/lo ----
    msda_kernel<<<32768, 256>>>(P, rb);
    // ---- cv2 (out-proj folded): K = catT[0:1024) ++ sdT[0:256) -> out fp32 NCHW (SiLU) ----
    gemm_tc<<<dim3(4, 32, NB), 256, SMEM_DYN>>>(catT_h, catT_l, 1024, 0,
        sdT_h, sdT_l, 256, 16, Wcv2, 20, 0,
        out, nullptr, nullptr, 0, 0, biasF, 2, 1);
}

// round 11
// speedup vs baseline: 1.0803x; 1.0803x over previous
#include <cuda_runtime.h>
#include <cuda_bf16.h>
#include <stdint.h>
#include <math.h>

#define NB 8
#define NL 4096
#define CCAT 1152   // padded concat channel stride (1024 used)

// ================= scratch (device globals) =================
__device__ __align__(1024) __nv_bfloat16 g_xT_hi[(size_t)NB * NL * 512];
__device__ __align__(1024) __nv_bfloat16 g_xT_lo[(size_t)NB * NL * 512];
__device__ __align__(1024) __nv_bfloat16 g_catT_hi[(size_t)NB * NL * CCAT];
__device__ __align__(1024) __nv_bfloat16 g_catT_lo[(size_t)NB * NL * CCAT];
__device__ __align__(1024) __nv_bfloat16 g_tmpT_hi[(size_t)NB * NL * 256];
__device__ __align__(1024) __nv_bfloat16 g_tmpT_lo[(size_t)NB * NL * 256];
__device__ __align__(1024) __nv_bfloat16 g_sdT_hi[(size_t)NB * NL * 256];
__device__ __align__(1024) __nv_bfloat16 g_sdT_lo[(size_t)NB * NL * 256];
__device__ __align__(1024) float g_P[(size_t)NB * NL * 384];   // 256 val | 64 off | 32 aw | 32 pad
__device__ float g_bias384[384];
__device__ float g_biasF[512];                                  // folded cv2 bias
__device__ __align__(1024) float g_outwT[256 * 256];            // out_w transposed [c][d]

// Pre-swizzled weight tiles: [n_tile][stage][ hi 16KB | lo 16KB ]
// tile: 128 co rows x 64 bf16 K; row r at r*128 + (kbyte ^ ((r&7)*16))  (ldmatrix-ready)
__device__ __align__(1024) uint8_t g_Wcv1 [4  * 8  * 32768];   // 512 co, K=512
__device__ __align__(1024) uint8_t g_Wc   [4][2 * 36 * 32768]; // 256 co, K=2304 (9 taps x 256 ci)
__device__ __align__(1024) uint8_t g_Wproj[3  * 4  * 32768];   // 384 co (padded), K=256
__device__ __align__(1024) uint8_t g_Wcv2 [4  * 20 * 32768];   // 512 co, K=1280 (last 256 = folded out_w)

__device__ __forceinline__ float silu_f(float x) { return x / (1.0f + expf(-x)); }

// ================= PTX helpers (compute_103-safe) =================
__device__ __forceinline__ uint32_t smem_u32(const void* p) {
    uint32_t a;
    asm("{ .reg .u64 t; cvta.to.shared.u64 t, %1; cvt.u32.u64 %0, t; }" : "=r"(a) : "l"(p));
    return a;
}
#define CP_COMMIT() asm volatile("cp.async.commit_group;" ::: "memory")
#define CP_WAIT(n)  asm volatile("cp.async.wait_group %0;" :: "n"(n) : "memory")

__device__ __forceinline__ void cpa16(uint32_t d, const void* s, int sz) {
    asm volatile("cp.async.cg.shared.global [%0], [%1], 16, %2;"
                 :: "r"(d), "l"(s), "r"(sz) : "memory");
}
__device__ __forceinline__ void ldsm4(uint32_t a, uint32_t* r) {
    asm volatile("ldmatrix.sync.aligned.m8n8.x4.shared.b16 {%0,%1,%2,%3}, [%4];"
                 : "=r"(r[0]), "=r"(r[1]), "=r"(r[2]), "=r"(r[3]) : "r"(a));
}
__device__ __forceinline__ void mma16816(float* d, const uint32_t* a, const uint32_t* b) {
    asm volatile("mma.sync.aligned.m16n8k16.row.col.f32.bf16.bf16.f32 "
                 "{%0,%1,%2,%3}, {%4,%5,%6,%7}, {%8,%9}, {%0,%1,%2,%3};"
                 : "+f"(d[0]), "+f"(d[1]), "+f"(d[2]), "+f"(d[3])
                 : "r"(a[0]), "r"(a[1]), "r"(a[2]), "r"(a[3]), "r"(b[0]), "r"(b[1]));
}

// ================= weight prep =================
__device__ __forceinline__ void wstore(uint8_t* dst, int n_stages, int co, int k, float v) {
    int tile = co >> 7, rr = co & 127, st = k >> 6, kk = k & 63;
    __nv_bfloat16 h = __float2bfloat16(v);
    __nv_bfloat16 l = __float2bfloat16(v - __bfloat162float(h));
    size_t base = (size_t)(tile * n_stages + st) * 32768;
    uint32_t off = (uint32_t)(rr * 128 + ((kk * 2) ^ ((rr & 7) * 16)));
    *(__nv_bfloat16*)(dst + base + off) = h;
    *(__nv_bfloat16*)(dst + base + 16384 + off) = l;
}

__global__ void prep_cv1(const float* __restrict__ w) {
    int i = blockIdx.x * 256 + threadIdx.x;            // 512*512
    int co = i >> 9, k = i & 511;
    wstore(g_Wcv1, 8, co, k, w[co * 512 + k]);
}
__global__ void prep_conv(const float* __restrict__ w, uint8_t* __restrict__ dst) {
    int i = blockIdx.x * 256 + threadIdx.x;            // 256*2304
    int co = i / 2304, k = i - co * 2304;
    int tap = k >> 8, ci = k & 255;
    wstore(dst, 36, co, k, w[(co * 256 + ci) * 9 + tap]);
}
__global__ void prep_proj(const float* __restrict__ vw, const float* __restrict__ ow,
                          const float* __restrict__ aww) {
    int i = blockIdx.x * 256 + threadIdx.x;            // 384*256
    int co = i >> 8, k = i & 255;
    float v = (co < 256) ? vw[k * 256 + co]
            : (co < 320) ? ow[k * 64 + (co - 256)]
            : (co < 352) ? aww[k * 32 + (co - 320)] : 0.f;
    wstore(g_Wproj, 4, co, k, v);
}
__global__ void prep_bias(const float* __restrict__ vb, const float* __restrict__ ob,
                          const float* __restrict__ awb) {
    int j = blockIdx.x * 128 + threadIdx.x;
    if (j < 384)
        g_bias384[j] = (j < 256) ? vb[j] : (j < 320) ? ob[j - 256] : (j < 352) ? awb[j - 320] : 0.f;
}
__global__ void prep_cv2(const float* __restrict__ w) {
    int i = blockIdx.x * 256 + threadIdx.x;            // 512*1024 (first 16 stages)
    int co = i >> 10, k = i & 1023;
    wstore(g_Wcv2, 20, co, k, w[co * 1280 + k]);
}
// Transpose out_w to [c][d] so the fold kernel reads coalesced.
__global__ void transp_outw(const float* __restrict__ w) {
    __shared__ float t[32][33];
    int bx = blockIdx.x & 7, by = blockIdx.x >> 3;     // 64 blocks over 256x256
    int tx = threadIdx.x & 31, ty = threadIdx.x >> 5;  // 32x8
#pragma unroll
    for (int i = 0; i < 4; i++)
        t[ty + i * 8][tx] = w[(by * 32 + ty + i * 8) * 256 + bx * 32 + tx];
    __syncthreads();
#pragma unroll
    for (int i = 0; i < 4; i++)
        g_outwT[(bx * 32 + ty + i * 8) * 256 + by * 32 + tx] = t[tx][ty + i * 8];
}
// Fold out-projection into cv2: Wfold[o][d] = sum_c cv2_w[o][1024+c] * out_w[d][c]
// Reads outwT coalesced (lane d contiguous). Also folds bias in the same kernel.
__global__ void prep_fold(const float* __restrict__ cv2w, const float* __restrict__ outb) {
    __shared__ float srow[256];
    __shared__ float red[256];
    int o = blockIdx.x, d = threadIdx.x;
    float sv = cv2w[o * 1280 + 1024 + d];
    srow[d] = sv;
    red[d] = sv * outb[d];
    __syncthreads();
    float acc = 0.f;
#pragma unroll 4
    for (int c = 0; c < 256; c++) acc = fmaf(srow[c], g_outwT[c * 256 + d], acc);
    wstore(g_Wcv2, 20, o, 1024 + d, acc);
    for (int st = 128; st > 0; st >>= 1) {
        __syncthreads();
        if (d < st) red[d] += red[d + st];
    }
    if (d == 0) g_biasF[o] = red[0];
}

// ================= x -> xT hi/lo =================
__global__ void xT_kernel(const float* __restrict__ x) {
    __shared__ float t[32][33];
    int b = blockIdx.z;
    int p0 = blockIdx.x * 32, c0 = blockIdx.y * 32;
    int tx = threadIdx.x, ty = threadIdx.y;            // (32, 8)
    const float* xb = x + (size_t)b * 512 * 4096;
#pragma unroll
    for (int i = 0; i < 4; i++)
        t[ty + i * 8][tx] = xb[(size_t)(c0 + ty + i * 8) * 4096 + p0 + tx];
    __syncthreads();
#pragma unroll
    for (int i = 0; i < 4; i++) {
        int pp = p0 + ty + i * 8, cc = c0 + tx;
        float v = t[tx][ty + i * 8];
        __nv_bfloat16 h = __float2bfloat16(v);
        __nv_bfloat16 l = __float2bfloat16(v - __bfloat162float(h));
        size_t idx = ((size_t)b * 4096 + pp) * 512 + cc;
        g_xT_hi[idx] = h;
        g_xT_lo[idx] = l;
    }
}

// ================= tensor-core GEMM (mma.sync bf16, split hi/lo x3) =================
// R7-proven config: double buffer, per-accumulator interleaved MMA order.
// Stages >= splitS read from A2 (second activation tensor) — feeds cv2 from sdT.
__global__ void __launch_bounds__(256, 1)
gemm_tc(const __nv_bfloat16* __restrict__ A_hi, const __nv_bfloat16* __restrict__ A_lo,
        int Cs, int c0,
        const __nv_bfloat16* __restrict__ A2_hi, const __nv_bfloat16* __restrict__ A2_lo,
        int Cs2, int splitS,
        const uint8_t* __restrict__ W, int n_stages, int conv_mode,
        float* __restrict__ outF,
        __nv_bfloat16* __restrict__ O_hi, __nv_bfloat16* __restrict__ O_lo,
        int CsO, int c0O,
        const float* __restrict__ bias, int out_mode, int act)
{
    extern __shared__ uint8_t dyn[];
    uint8_t* dynp = dyn + ((1024u - (smem_u32(dyn) & 1023u)) & 1023u);
    uint32_t dynb = smem_u32(dynp);

    int tid = threadIdx.x;
    int lane = tid & 31, w = tid >> 5;
    int b = blockIdx.z, n_tile = blockIdx.x;
    int p0 = blockIdx.y * 128;

    const __nv_bfloat16* Ah = A_hi + (size_t)b * NL * Cs + c0;
    const __nv_bfloat16* Al = A_lo + (size_t)b * NL * Cs + c0;
    const __nv_bfloat16* A2h = A2_hi ? A2_hi + (size_t)b * NL * Cs2 : nullptr;
    const __nv_bfloat16* A2l = A2_lo ? A2_lo + (size_t)b * NL * Cs2 : nullptr;
    const uint8_t* Wt = W + (size_t)n_tile * n_stages * 32768;

    // ---- cp.async stage loader (double buffer) ----
    auto issue = [&](int s, int buf) {
        uint32_t bo = dynb + buf * 65536;
        const __nv_bfloat16 *ah, *al;
        int cs, ci0, ky = 0, kx = 0;
        if (s >= splitS) {
            ah = A2h; al = A2l; cs = Cs2; ci0 = (s - splitS) * 64;
        } else if (conv_mode) {
            int tap = s >> 2; ky = tap / 3; kx = tap - ky * 3;
            ah = Ah; al = Al; cs = Cs; ci0 = (s & 3) * 64;
        } else {
            ah = Ah; al = Al; cs = Cs; ci0 = s * 64;
        }
#pragma unroll
        for (int t = 0; t < 4; t++) {
            int f = tid + t * 256;                    // 0..1023
            int row = f >> 3, q = f & 7;
            int p = p0 + row;
            int psrc = p, valid = 1;
            if (conv_mode && s < splitS) {
                int yy = (p >> 6) + ky - 1, xx = (p & 63) + kx - 1;
                valid = ((unsigned)yy < 64u) && ((unsigned)xx < 64u);
                psrc = valid ? (p + (ky - 1) * 64 + (kx - 1)) : p;
            }
            uint32_t off = (uint32_t)(row * 128 + ((q * 16) ^ ((row & 7) * 16)));
            int sz = valid ? 16 : 0;
            cpa16(bo + off,         ah + (size_t)psrc * cs + ci0 + q * 8, sz);
            cpa16(bo + 16384 + off, al + (size_t)psrc * cs + ci0 + q * 8, sz);
        }
        const uint8_t* ws = Wt + (size_t)s * 32768;
#pragma unroll
        for (int t = 0; t < 8; t++) {
            int f = tid + t * 256;                    // 0..2047 -> 32KB (hi+lo)
            cpa16(bo + 32768 + f * 16, ws + f * 16, 16);
        }
    };

    // ---- per-lane ldmatrix bases ----
    int lr = lane & 7, g = lane >> 3;
    int m0w = (w & 3) * 32, n0w = (w >> 2) * 64;
    uint32_t xorv = (uint32_t)(lr * 16);
    int kfixA = (g >> 1) * 16;
    int rowA = m0w + (g & 1) * 8 + lr;
    uint32_t aBase[2];
    aBase[0] = dynb + (uint32_t)(rowA * 128);
    aBase[1] = dynb + (uint32_t)((rowA + 16) * 128);
    int kfixB = (g & 1) * 16;
    uint32_t bBase[4];
#pragma unroll
    for (int bp = 0; bp < 4; bp++) {
        int rowB = n0w + bp * 16 + (g >> 1) * 8 + lr;
        bBase[bp] = dynb + 32768u + (uint32_t)(rowB * 128);
    }

    float acc[2][8][4];
#pragma unroll
    for (int mi = 0; mi < 2; mi++)
#pragma unroll
        for (int ng = 0; ng < 8; ng++)
#pragma unroll
            for (int q = 0; q < 4; q++) acc[mi][ng][q] = 0.f;

    issue(0, 0); CP_COMMIT();

    for (int s = 0; s < n_stages; s++) {
        int buf = s & 1;
        if (s + 1 < n_stages) { issue(s + 1, buf ^ 1); CP_COMMIT(); CP_WAIT(1); }
        else                  { CP_WAIT(0); }
        __syncthreads();

        uint32_t bo = (uint32_t)(buf * 65536);
#pragma unroll
        for (int kk8 = 0; kk8 < 4; kk8++) {
            int kb = kk8 * 32;
            uint32_t ka  = (uint32_t)((kb + kfixA) ^ (int)xorv);
            uint32_t kbb = (uint32_t)((kb + kfixB) ^ (int)xorv);
            uint32_t ahf[2][4], alf[2][4];
            ldsm4(aBase[0] + bo + ka,          ahf[0]);
            ldsm4(aBase[1] + bo + ka,          ahf[1]);
            ldsm4(aBase[0] + 16384 + bo + ka,  alf[0]);
            ldsm4(aBase[1] + 16384 + bo + ka,  alf[1]);
            uint32_t bhf[4][4], blf[4][4];
#pragma unroll
            for (int bp = 0; bp < 4; bp++) {
                ldsm4(bBase[bp] + bo + kbb,         bhf[bp]);
                ldsm4(bBase[bp] + 16384 + bo + kbb, blf[bp]);
            }
#pragma unroll
            for (int mi = 0; mi < 2; mi++)
#pragma unroll
                for (int ng = 0; ng < 8; ng++) {
                    const uint32_t* bh = &bhf[ng >> 1][(ng & 1) * 2];
                    const uint32_t* bl = &blf[ng >> 1][(ng & 1) * 2];
                    mma16816(acc[mi][ng], ahf[mi], bh);   // hi*hi
                    mma16816(acc[mi][ng], ahf[mi], bl);   // hi*lo
                    mma16816(acc[mi][ng], alf[mi], bh);   // lo*hi
                }
        }
        __syncthreads();
    }

    // ---- epilogue ----
    int prb = p0 + m0w + (lane >> 2);
    int colb = n0w + 2 * (lane & 3);
#pragma unroll
    for (int mi = 0; mi < 2; mi++)
#pragma unroll
        for (int ng = 0; ng < 8; ng++) {
            int cog = n_tile * 128 + colb + ng * 8;
#pragma unroll
            for (int half = 0; half < 2; half++) {
                int pe = prb + mi * 16 + half * 8;
                float v0 = acc[mi][ng][half * 2 + 0];
                float v1 = acc[mi][ng][half * 2 + 1];
                if (out_mode == 0) {
                    if (bias) { v0 += bias[cog]; v1 += bias[cog + 1]; }
                    if (act)  { v0 = silu_f(v0); v1 = silu_f(v1); }
                    __nv_bfloat16 h0 = __float2bfloat16(v0), h1 = __float2bfloat16(v1);
                    __nv_bfloat16 l0 = __float2bfloat16(v0 - __bfloat162float(h0));
                    __nv_bfloat16 l1 = __float2bfloat16(v1 - __bfloat162float(h1));
                    uint32_t hp = (uint32_t)__bfloat16_as_ushort(h0) | ((uint32_t)__bfloat16_as_ushort(h1) << 16);
                    uint32_t lp = (uint32_t)__bfloat16_as_ushort(l0) | ((uint32_t)__bfloat16_as_ushort(l1) << 16);
                    size_t ob = ((size_t)b * NL + pe) * CsO + c0O + cog;
                    *(uint32_t*)(O_hi + ob) = hp;
                    *(uint32_t*)(O_lo + ob) = lp;
                } else if (out_mode == 1) {
                    float2 v;
                    v.x = v0 + bias[cog];
                    v.y = v1 + bias[cog + 1];
                    *(float2*)&outF[((size_t)b * NL + pe) * 384 + cog] = v;
                } else {
                    float b0 = bias ? bias[cog] : 0.f;
                    float b1 = bias ? bias[cog + 1] : 0.f;
                    outF[((size_t)(b * 512 + cog)     << 12) + pe] = silu_f(v0 + b0);
                    outF[((size_t)(b * 512 + cog + 1) << 12) + pe] = silu_f(v1 + b1);
                }
            }
        }
}

// ================= deformable sampling =================
__global__ void msda_kernel(const float* __restrict__ P, const float* __restrict__ rb)
{
    int warp = threadIdx.x >> 5;
    int lane = threadIdx.x & 31;
    long long gw = (long long)blockIdx.x * 8 + warp;
    int h = (int)(gw & 7);
    long long bl = gw >> 3;
    long long b = bl >> 12;
    const float* Pl = P + bl * 384;
    const float* Vb = P + b * (long long)NL * 384;
    float rbx = rb[bl * 2 + 0];
    float rby = rb[bl * 2 + 1];

    float lg[4];
    float mx = -1e30f;
#pragma unroll
    for (int pp = 0; pp < 4; pp++) { lg[pp] = Pl[320 + h * 4 + pp]; mx = fmaxf(mx, lg[pp]); }
    float s = 0.f;
#pragma unroll
    for (int pp = 0; pp < 4; pp++) { lg[pp] = expf(lg[pp] - mx); s += lg[pp]; }
    float inv = 1.f / s;

    int hoff = h * 32 + lane;
    float acc = 0.f;
#pragma unroll
    for (int pp = 0; pp < 4; pp++) {
        float ox = Pl[256 + h * 8 + pp * 2 + 0];
        float oy = Pl[256 + h * 8 + pp * 2 + 1];
        float gx = (rbx + ox * (1.f / 64.f)) * 64.f - 0.5f;
        float gy = (rby + oy * (1.f / 64.f)) * 64.f - 0.5f;
        float x0f = floorf(gx), y0f = floorf(gy);
        int x0 = (int)x0f, y0 = (int)y0f;
        float wx1 = gx - x0f, wy1 = gy - y0f;
        float wx0 = 1.f - wx1, wy0 = 1.f - wy1;

        float v00 = 0.f, v10 = 0.f, v01 = 0.f, v11 = 0.f;
        if ((unsigned)x0       < 64u && (unsigned)y0       < 64u) v00 = Vb[(long long)(y0 * 64 + x0) * 384 + hoff];
        if ((unsigned)(x0 + 1) < 64u && (unsigned)y0       < 64u) v10 = Vb[(long long)(y0 * 64 + x0 + 1) * 384 + hoff];
        if ((unsigned)x0       < 64u && (unsigned)(y0 + 1) < 64u) v01 = Vb[(long long)((y0 + 1) * 64 + x0) * 384 + hoff];
        if ((unsigned)(x0 + 1) < 64u && (unsigned)(y0 + 1) < 64u) v11 = Vb[(long long)((y0 + 1) * 64 + x0 + 1) * 384 + hoff];

        float sv = v00 * (wx0 * wy0) + v10 * (wx1 * wy0) + v01 * (wx0 * wy1) + v11 * (wx1 * wy1);
        acc = fmaf(lg[pp] * inv, sv, acc);
    }
    __nv_bfloat16 hv = __float2bfloat16(acc);
    __nv_bfloat16 lv = __float2bfloat16(acc - __bfloat162float(hv));
    size_t idx = (size_t)bl * 256 + hoff;
    g_sdT_hi[idx] = hv;
    g_sdT_lo[idx] = lv;
}

// ================= launch =================
extern "C" void kernel_launch(void* const* d_in, const int* in_sizes, int n_in,
                              void* d_out, int out_size)
{
    const float* x       = (const float*)d_in[0];
    const float* rb      = (const float*)d_in[1];
    const float* cv1_w   = (const float*)d_in[3];
    const float* m0c1    = (const float*)d_in[4];
    const float* m0c2    = (const float*)d_in[5];
    const float* m1c1    = (const float*)d_in[6];
    const float* m1c2    = (const float*)d_in[7];
    const float* vproj_w = (const float*)d_in[8];
    const float* vproj_b = (const float*)d_in[9];
    const float* off_w   = (const float*)d_in[10];
    const float* off_b   = (const float*)d_in[11];
    const float* aw_w    = (const float*)d_in[12];
    const float* aw_b    = (const float*)d_in[13];
    const float* out_w   = (const float*)d_in[14];
    const float* out_b   = (const float*)d_in[15];
    const float* cv2_w   = (const float*)d_in[16];
    float* out = (float*)d_out;

    __nv_bfloat16 *xT_h, *xT_l, *catT_h, *catT_l, *tmpT_h, *tmpT_l, *sdT_h, *sdT_l;
    float *P, *bias384, *biasF;
    uint8_t *Wcv1, *Wc, *Wproj, *Wcv2;
    cudaGetSymbolAddress((void**)&xT_h,   g_xT_hi);
    cudaGetSymbolAddress((void**)&xT_l,   g_xT_lo);
    cudaGetSymbolAddress((void**)&catT_h, g_catT_hi);
    cudaGetSymbolAddress((void**)&catT_l, g_catT_lo);
    cudaGetSymbolAddress((void**)&tmpT_h, g_tmpT_hi);
    cudaGetSymbolAddress((void**)&tmpT_l, g_tmpT_lo);
    cudaGetSymbolAddress((void**)&sdT_h,  g_sdT_hi);
    cudaGetSymbolAddress((void**)&sdT_l,  g_sdT_lo);
    cudaGetSymbolAddress((void**)&P,      g_P);
    cudaGetSymbolAddress((void**)&bias384,g_bias384);
    cudaGetSymbolAddress((void**)&biasF,  g_biasF);
    cudaGetSymbolAddress((void**)&Wcv1,   g_Wcv1);
    cudaGetSymbolAddress((void**)&Wc,     g_Wc);
    cudaGetSymbolAddress((void**)&Wproj,  g_Wproj);
    cudaGetSymbolAddress((void**)&Wcv2,   g_Wcv2);

    const int SMEM_DYN = 2 * 65536 + 1024;
    cudaFuncSetAttribute(gemm_tc, cudaFuncAttributeMaxDynamicSharedMemorySize, SMEM_DYN);

    const size_t WCS = 2ull * 36 * 32768;
    const int BIG = 1 << 30;

    // ---- prep ----
    prep_cv1 <<<1024, 256>>>(cv1_w);
    prep_conv<<<2304, 256>>>(m0c1, Wc + 0 * WCS);
    prep_conv<<<2304, 256>>>(m0c2, Wc + 1 * WCS);
    prep_conv<<<2304, 256>>>(m1c1, Wc + 2 * WCS);
    prep_conv<<<2304, 256>>>(m1c2, Wc + 3 * WCS);
    prep_proj<<<384, 256>>>(vproj_w, off_w, aw_w);
    prep_bias<<<3, 128>>>(vproj_b, off_b, aw_b);
    prep_cv2 <<<2048, 256>>>(cv2_w);
    transp_outw<<<64, 256>>>(out_w);
    prep_fold<<<512, 256>>>(cv2_w, out_b);
    xT_kernel<<<dim3(128, 16, NB), dim3(32, 8)>>>(x);

    // ---- cv1: xT[512] -> catT[0:512) (SiLU) ----
    gemm_tc<<<dim3(4, 32, NB), 256, SMEM_DYN>>>(xT_h, xT_l, 512, 0,
        nullptr, nullptr, 0, BIG, Wcv1, 8, 0,
        nullptr, catT_h, catT_l, CCAT, 0, nullptr, 0, 1);
    // ---- conv0: catT b[256:512) -> tmpT (SiLU) ----
    gemm_tc<<<dim3(2, 32, NB), 256, SMEM_DYN>>>(catT_h, catT_l, CCAT, 256,
        nullptr, nullptr, 0, BIG, Wc + 0 * WCS, 36, 1,
        nullptr, tmpT_h, tmpT_l, 256, 0, nullptr, 0, 1);
    // ---- conv1: tmpT -> catT b1[512:768) (SiLU) ----
    gemm_tc<<<dim3(2, 32, NB), 256, SMEM_DYN>>>(tmpT_h, tmpT_l, 256, 0,
        nullptr, nullptr, 0, BIG, Wc + 1 * WCS, 36, 1,
        nullptr, catT_h, catT_l, CCAT, 512, nullptr, 0, 1);
    // ---- conv2: catT b1 -> tmpT (SiLU) ----
    gemm_tc<<<dim3(2, 32, NB), 256, SMEM_DYN>>>(catT_h, catT_l, CCAT, 512,
        nullptr, nullptr, 0, BIG, Wc + 2 * WCS, 36, 1,
        nullptr, tmpT_h, tmpT_l, 256, 0, nullptr, 0, 1);
    // ---- conv3: tmpT -> catT b2[768:1024) (SiLU) ----
    gemm_tc<<<dim3(2, 32, NB), 256, SMEM_DYN>>>(tmpT_h, tmpT_l, 256, 0,
        nullptr, nullptr, 0, BIG, Wc + 3 * WCS, 36, 1,
        nullptr, catT_h, catT_l, CCAT, 768, nullptr, 0, 1);
    // ---- proj: catT b2 -> P[b][p][384] (+bias) ----
    gemm_tc<<<dim3(3, 32, NB), 256, SMEM_DYN>>>(catT_h, catT_l, CCAT, 768,
        nullptr, nullptr, 0, BIG, Wproj, 4, 0,
        P, nullptr, nullptr, 0, 0, bias384, 1, 0);
    // ---- deformable sampling -> sdT hi/lo ----
    msda_kernel<<<32768, 256>>>(P, rb);
    // ---- cv2 (out-proj folded): K = catT[0:1024) ++ sdT[0:256) -> out fp32 NCHW (SiLU) ----
    gemm_tc<<<dim3(4, 32, NB), 256, SMEM_DYN>>>(catT_h, catT_l, CCAT, 0,
        sdT_h, sdT_l, 256, 16, Wcv2, 20, 0,
        out, nullptr, nullptr, 0, 0, biasF, 2, 1);
}

// round 12
// speedup vs baseline: 1.2085x; 1.1187x over previous
#include <cuda_runtime.h>
#include <cuda_bf16.h>
#include <stdint.h>
#include <math.h>

#define NB 8
#define NL 4096
#define CCAT 1152   // padded concat channel stride (1024 used)

// ================= scratch (device globals) =================
__device__ __align__(1024) __nv_bfloat16 g_xT_hi[(size_t)NB * NL * 512];
__device__ __align__(1024) __nv_bfloat16 g_xT_lo[(size_t)NB * NL * 512];
__device__ __align__(1024) __nv_bfloat16 g_catT_hi[(size_t)NB * NL * CCAT];
__device__ __align__(1024) __nv_bfloat16 g_catT_lo[(size_t)NB * NL * CCAT];
__device__ __align__(1024) __nv_bfloat16 g_tmpT_hi[(size_t)NB * NL * 256];
__device__ __align__(1024) __nv_bfloat16 g_tmpT_lo[(size_t)NB * NL * 256];
__device__ __align__(1024) __nv_bfloat16 g_sdT_hi[(size_t)NB * NL * 256];
__device__ __align__(1024) __nv_bfloat16 g_sdT_lo[(size_t)NB * NL * 256];
__device__ __align__(1024) float g_P[(size_t)NB * NL * 384];   // 256 val | 64 off | 32 aw | 32 pad
__device__ float g_bias384[384];
__device__ float g_biasF[512];                                  // folded cv2 bias
__device__ __align__(1024) float g_outwT[256 * 256];            // out_w transposed [c][d]

// Pre-swizzled weight tiles: [n_tile][stage][ hi | lo ], tile = NT co rows x 64 bf16 K
// row r at r*128 + (kbyte ^ ((r&7)*16))  (ldmatrix-ready)
__device__ __align__(1024) uint8_t g_Wcv1 [4  * 8  * 32768];   // NT=128: 512 co, K=512
__device__ __align__(1024) uint8_t g_Wc   [4][4 * 36 * 16384]; // NT=64: 256 co, K=2304
__device__ __align__(1024) uint8_t g_Wproj[3  * 4  * 32768];   // NT=128: 384 co (pad), K=256
__device__ __align__(1024) uint8_t g_Wcv2 [4  * 20 * 32768];   // NT=128: 512 co, K=1280 (last 256 = folded)

__device__ __forceinline__ float silu_f(float x) { return x / (1.0f + expf(-x)); }

// ================= PTX helpers (compute_103-safe) =================
__device__ __forceinline__ uint32_t smem_u32(const void* p) {
    uint32_t a;
    asm("{ .reg .u64 t; cvta.to.shared.u64 t, %1; cvt.u32.u64 %0, t; }" : "=r"(a) : "l"(p));
    return a;
}
#define CP_COMMIT() asm volatile("cp.async.commit_group;" ::: "memory")
#define CP_WAIT(n)  asm volatile("cp.async.wait_group %0;" :: "n"(n) : "memory")

__device__ __forceinline__ void cpa16(uint32_t d, const void* s, int sz) {
    asm volatile("cp.async.cg.shared.global [%0], [%1], 16, %2;"
                 :: "r"(d), "l"(s), "r"(sz) : "memory");
}
__device__ __forceinline__ void ldsm4(uint32_t a, uint32_t* r) {
    asm volatile("ldmatrix.sync.aligned.m8n8.x4.shared.b16 {%0,%1,%2,%3}, [%4];"
                 : "=r"(r[0]), "=r"(r[1]), "=r"(r[2]), "=r"(r[3]) : "r"(a));
}
__device__ __forceinline__ void mma16816(float* d, const uint32_t* a, const uint32_t* b) {
    asm volatile("mma.sync.aligned.m16n8k16.row.col.f32.bf16.bf16.f32 "
                 "{%0,%1,%2,%3}, {%4,%5,%6,%7}, {%8,%9}, {%0,%1,%2,%3};"
                 : "+f"(d[0]), "+f"(d[1]), "+f"(d[2]), "+f"(d[3])
                 : "r"(a[0]), "r"(a[1]), "r"(a[2]), "r"(a[3]), "r"(b[0]), "r"(b[1]));
}

// ================= weight store (tile height NT) =================
__device__ __forceinline__ void wstore_t(uint8_t* dst, int n_stages, int NT, int co, int k, float v) {
    int tile = co / NT, rr = co % NT, st = k >> 6, kk = k & 63;
    __nv_bfloat16 h = __float2bfloat16(v);
    __nv_bfloat16 l = __float2bfloat16(v - __bfloat162float(h));
    size_t base = (size_t)(tile * n_stages + st) * (NT * 256);
    uint32_t off = (uint32_t)(rr * 128 + ((kk * 2) ^ ((rr & 7) * 16)));
    *(__nv_bfloat16*)(dst + base + off) = h;
    *(__nv_bfloat16*)(dst + base + NT * 128 + off) = l;
}

// ================= merged prep kernel =================
// segments: [0,1024) cv1 | [1024,10240) conv x4 | [10240,10624) proj |
//           [10624,10626) bias | [10626,12674) cv2 | [12674,12738) transp_outw |
//           [12738,29122) xT
__global__ void prep_all(const float* __restrict__ cv1w,
                         const float* __restrict__ c0w, const float* __restrict__ c1w,
                         const float* __restrict__ c2w, const float* __restrict__ c3w,
                         const float* __restrict__ vw, const float* __restrict__ vb,
                         const float* __restrict__ ow, const float* __restrict__ ob,
                         const float* __restrict__ aww, const float* __restrict__ awb,
                         const float* __restrict__ outw,
                         const float* __restrict__ cv2w,
                         const float* __restrict__ x)
{
    int bid = blockIdx.x, tid = threadIdx.x;
    if (bid < 1024) {                                    // cv1 (NT=128)
        int i = bid * 256 + tid;
        int co = i >> 9, k = i & 511;
        wstore_t(g_Wcv1, 8, 128, co, k, cv1w[co * 512 + k]);
    } else if (bid < 10240) {                            // convs (NT=64)
        int seg = (bid - 1024) / 2304;
        int i = ((bid - 1024) - seg * 2304) * 256 + tid;
        int co = i / 2304, k = i - co * 2304;
        int tap = k >> 8, ci = k & 255;
        const float* w = (seg == 0) ? c0w : (seg == 1) ? c1w : (seg == 2) ? c2w : c3w;
        wstore_t(&g_Wc[seg][0], 36, 64, co, k, w[(co * 256 + ci) * 9 + tap]);
    } else if (bid < 10624) {                            // proj (NT=128)
        int i = (bid - 10240) * 256 + tid;
        int co = i >> 8, k = i & 255;
        float v = (co < 256) ? vw[k * 256 + co]
                : (co < 320) ? ow[k * 64 + (co - 256)]
                : (co < 352) ? aww[k * 32 + (co - 320)] : 0.f;
        wstore_t(g_Wproj, 4, 128, co, k, v);
    } else if (bid < 10626) {                            // bias384
        int j = (bid - 10624) * 256 + tid;
        if (j < 384)
            g_bias384[j] = (j < 256) ? vb[j] : (j < 320) ? ob[j - 256] : (j < 352) ? awb[j - 320] : 0.f;
    } else if (bid < 12674) {                            // cv2 first 1024 K (NT=128)
        int i = (bid - 10626) * 256 + tid;
        int co = i >> 10, k = i & 1023;
        wstore_t(g_Wcv2, 20, 128, co, k, cv2w[co * 1280 + k]);
    } else if (bid < 12738) {                            // transpose out_w
        __shared__ float t[32][33];
        int bb = bid - 12674;
        int bx = bb & 7, by = bb >> 3;
        int tx = tid & 31, ty = tid >> 5;
#pragma unroll
        for (int i = 0; i < 4; i++)
            t[ty + i * 8][tx] = outw[(by * 32 + ty + i * 8) * 256 + bx * 32 + tx];
        __syncthreads();
#pragma unroll
        for (int i = 0; i < 4; i++)
            g_outwT[(bx * 32 + ty + i * 8) * 256 + by * 32 + tx] = t[tx][ty + i * 8];
    } else {                                             // xT transpose + split
        __shared__ float t[32][33];
        int idx = bid - 12738;
        int b = idx >> 11;
        int rem = idx & 2047;
        int p0 = (rem & 127) * 32, c0 = (rem >> 7) * 32;
        int tx = tid & 31, ty = tid >> 5;
        const float* xb = x + (size_t)b * 512 * 4096;
#pragma unroll
        for (int i = 0; i < 4; i++)
            t[ty + i * 8][tx] = xb[(size_t)(c0 + ty + i * 8) * 4096 + p0 + tx];
        __syncthreads();
#pragma unroll
        for (int i = 0; i < 4; i++) {
            int pp = p0 + ty + i * 8, cc = c0 + tx;
            float v = t[tx][ty + i * 8];
            __nv_bfloat16 h = __float2bfloat16(v);
            __nv_bfloat16 l = __float2bfloat16(v - __bfloat162float(h));
            size_t idx2 = ((size_t)b * 4096 + pp) * 512 + cc;
            g_xT_hi[idx2] = h;
            g_xT_lo[idx2] = l;
        }
    }
}

// Fold out-projection into cv2 (reads g_outwT coalesced); also folds bias.
__global__ void prep_fold(const float* __restrict__ cv2w, const float* __restrict__ outb) {
    __shared__ float srow[256];
    __shared__ float red[256];
    int o = blockIdx.x, d = threadIdx.x;
    float sv = cv2w[o * 1280 + 1024 + d];
    srow[d] = sv;
    red[d] = sv * outb[d];
    __syncthreads();
    float acc = 0.f;
#pragma unroll 4
    for (int c = 0; c < 256; c++) acc = fmaf(srow[c], g_outwT[c * 256 + d], acc);
    wstore_t(g_Wcv2, 20, 128, o, 1024 + d, acc);
    for (int st = 128; st > 0; st >>= 1) {
        __syncthreads();
        if (d < st) red[d] += red[d + st];
    }
    if (d == 0) g_biasF[o] = red[0];
}

// ================= tensor-core GEMM (mma.sync bf16, split hi/lo x3) =================
// Template NT = N tile (64 or 128). NT=64 -> 48KB/stage -> 2 CTAs/SM.
// Stages >= splitS read from A2 (second activation tensor) — feeds cv2 from sdT.
template <int NT>
__global__ void __launch_bounds__(256, NT == 64 ? 2 : 1)
gemm_tc(const __nv_bfloat16* __restrict__ A_hi, const __nv_bfloat16* __restrict__ A_lo,
        int Cs, int c0,
        const __nv_bfloat16* __restrict__ A2_hi, const __nv_bfloat16* __restrict__ A2_lo,
        int Cs2, int splitS,
        const uint8_t* __restrict__ W, int n_stages, int conv_mode,
        float* __restrict__ outF,
        __nv_bfloat16* __restrict__ O_hi, __nv_bfloat16* __restrict__ O_lo,
        int CsO, int c0O,
        const float* __restrict__ bias, int out_mode, int act)
{
    constexpr int NG  = NT / 16;            // n-groups of 8 cols per thread
    constexpr int NBP = NT / 32;            // B ldmatrix row-pair groups
    constexpr int SBYTES = 32768 + NT * 256; // stage bytes (A 32K + B hi/lo)
    extern __shared__ uint8_t dyn[];
    uint8_t* dynp = dyn + ((1024u - (smem_u32(dyn) & 1023u)) & 1023u);
    uint32_t dynb = smem_u32(dynp);

    int tid = threadIdx.x;
    int lane = tid & 31, w = tid >> 5;
    int b = blockIdx.z, n_tile = blockIdx.x;
    int p0 = blockIdx.y * 128;

    const __nv_bfloat16* Ah = A_hi + (size_t)b * NL * Cs + c0;
    const __nv_bfloat16* Al = A_lo + (size_t)b * NL * Cs + c0;
    const __nv_bfloat16* A2h = A2_hi ? A2_hi + (size_t)b * NL * Cs2 : nullptr;
    const __nv_bfloat16* A2l = A2_lo ? A2_lo + (size_t)b * NL * Cs2 : nullptr;
    const uint8_t* Wt = W + (size_t)n_tile * n_stages * (NT * 256);

    // ---- cp.async stage loader (double buffer) ----
    auto issue = [&](int s, int buf) {
        uint32_t bo = dynb + buf * SBYTES;
        const __nv_bfloat16 *ah, *al;
        int cs, ci0, ky = 0, kx = 0;
        if (s >= splitS) {
            ah = A2h; al = A2l; cs = Cs2; ci0 = (s - splitS) * 64;
        } else if (conv_mode) {
            int tap = s >> 2; ky = tap / 3; kx = tap - ky * 3;
            ah = Ah; al = Al; cs = Cs; ci0 = (s & 3) * 64;
        } else {
            ah = Ah; al = Al; cs = Cs; ci0 = s * 64;
        }
#pragma unroll
        for (int t = 0; t < 4; t++) {
            int f = tid + t * 256;                    // 0..1023
            int row = f >> 3, q = f & 7;
            int p = p0 + row;
            int psrc = p, valid = 1;
            if (conv_mode && s < splitS) {
                int yy = (p >> 6) + ky - 1, xx = (p & 63) + kx - 1;
                valid = ((unsigned)yy < 64u) && ((unsigned)xx < 64u);
                psrc = valid ? (p + (ky - 1) * 64 + (kx - 1)) : p;
            }
            uint32_t off = (uint32_t)(row * 128 + ((q * 16) ^ ((row & 7) * 16)));
            int sz = valid ? 16 : 0;
            cpa16(bo + off,         ah + (size_t)psrc * cs + ci0 + q * 8, sz);
            cpa16(bo + 16384 + off, al + (size_t)psrc * cs + ci0 + q * 8, sz);
        }
        const uint8_t* ws = Wt + (size_t)s * (NT * 256);
#pragma unroll
        for (int t = 0; t < NT / 16; t++) {
            int f = tid + t * 256;                    // linear copy of pre-swizzled B image
            cpa16(bo + 32768 + f * 16, ws + f * 16, 16);
        }
    };

    // ---- per-lane ldmatrix bases ----
    int lr = lane & 7, g = lane >> 3;
    int m0w = (w & 3) * 32, n0w = (w >> 2) * (NT >> 1);
    uint32_t xorv = (uint32_t)(lr * 16);
    int kfixA = (g >> 1) * 16;
    int rowA = m0w + (g & 1) * 8 + lr;
    uint32_t aBase[2];
    aBase[0] = dynb + (uint32_t)(rowA * 128);
    aBase[1] = dynb + (uint32_t)((rowA + 16) * 128);
    int kfixB = (g & 1) * 16;
    uint32_t bBase[NBP];
#pragma unroll
    for (int bp = 0; bp < NBP; bp++) {
        int rowB = n0w + bp * 16 + (g >> 1) * 8 + lr;
        bBase[bp] = dynb + 32768u + (uint32_t)(rowB * 128);
    }

    float acc[2][NG][4];
#pragma unroll
    for (int mi = 0; mi < 2; mi++)
#pragma unroll
        for (int ng = 0; ng < NG; ng++)
#pragma unroll
            for (int q = 0; q < 4; q++) acc[mi][ng][q] = 0.f;

    issue(0, 0); CP_COMMIT();

    for (int s = 0; s < n_stages; s++) {
        int buf = s & 1;
        if (s + 1 < n_stages) { issue(s + 1, buf ^ 1); CP_COMMIT(); CP_WAIT(1); }
        else                  { CP_WAIT(0); }
        __syncthreads();

        uint32_t bo = (uint32_t)(buf * SBYTES);
#pragma unroll
        for (int kk8 = 0; kk8 < 4; kk8++) {
            int kb = kk8 * 32;
            uint32_t ka  = (uint32_t)((kb + kfixA) ^ (int)xorv);
            uint32_t kbb = (uint32_t)((kb + kfixB) ^ (int)xorv);
            uint32_t ahf[2][4], alf[2][4];
            ldsm4(aBase[0] + bo + ka,          ahf[0]);
            ldsm4(aBase[1] + bo + ka,          ahf[1]);
            ldsm4(aBase[0] + 16384 + bo + ka,  alf[0]);
            ldsm4(aBase[1] + 16384 + bo + ka,  alf[1]);
            uint32_t bhf[NBP][4], blf[NBP][4];
#pragma unroll
            for (int bp = 0; bp < NBP; bp++) {
                ldsm4(bBase[bp] + bo + kbb,            bhf[bp]);
                ldsm4(bBase[bp] + NT * 128 + bo + kbb, blf[bp]);
            }
#pragma unroll
            for (int mi = 0; mi < 2; mi++)
#pragma unroll
                for (int ng = 0; ng < NG; ng++) {
                    const uint32_t* bh = &bhf[ng >> 1][(ng & 1) * 2];
                    const uint32_t* bl = &blf[ng >> 1][(ng & 1) * 2];
                    mma16816(acc[mi][ng], ahf[mi], bh);   // hi*hi
                    mma16816(acc[mi][ng], ahf[mi], bl);   // hi*lo
                    mma16816(acc[mi][ng], alf[mi], bh);   // lo*hi
                }
        }
        __syncthreads();
    }

    // ---- epilogue ----
    int prb = p0 + m0w + (lane >> 2);
    int colb = n0w + 2 * (lane & 3);
#pragma unroll
    for (int mi = 0; mi < 2; mi++)
#pragma unroll
        for (int ng = 0; ng < NG; ng++) {
            int cog = n_tile * NT + colb + ng * 8;
#pragma unroll
            for (int half = 0; half < 2; half++) {
                int pe = prb + mi * 16 + half * 8;
                float v0 = acc[mi][ng][half * 2 + 0];
                float v1 = acc[mi][ng][half * 2 + 1];
                if (out_mode == 0) {
                    if (bias) { v0 += bias[cog]; v1 += bias[cog + 1]; }
                    if (act)  { v0 = silu_f(v0); v1 = silu_f(v1); }
                    __nv_bfloat16 h0 = __float2bfloat16(v0), h1 = __float2bfloat16(v1);
                    __nv_bfloat16 l0 = __float2bfloat16(v0 - __bfloat162float(h0));
                    __nv_bfloat16 l1 = __float2bfloat16(v1 - __bfloat162float(h1));
                    uint32_t hp = (uint32_t)__bfloat16_as_ushort(h0) | ((uint32_t)__bfloat16_as_ushort(h1) << 16);
                    uint32_t lp = (uint32_t)__bfloat16_as_ushort(l0) | ((uint32_t)__bfloat16_as_ushort(l1) << 16);
                    size_t ob = ((size_t)b * NL + pe) * CsO + c0O + cog;
                    *(uint32_t*)(O_hi + ob) = hp;
                    *(uint32_t*)(O_lo + ob) = lp;
                } else if (out_mode == 1) {
                    float2 v;
                    v.x = v0 + bias[cog];
                    v.y = v1 + bias[cog + 1];
                    *(float2*)&outF[((size_t)b * NL + pe) * 384 + cog] = v;
                } else {
                    float b0 = bias ? bias[cog] : 0.f;
                    float b1 = bias ? bias[cog + 1] : 0.f;
                    outF[((size_t)(b * 512 + cog)     << 12) + pe] = silu_f(v0 + b0);
                    outF[((size_t)(b * 512 + cog + 1) << 12) + pe] = silu_f(v1 + b1);
                }
            }
        }
}

// ================= deformable sampling =================
__global__ void msda_kernel(const float* __restrict__ P, const float* __restrict__ rb)
{
    int warp = threadIdx.x >> 5;
    int lane = threadIdx.x & 31;
    long long gw = (long long)blockIdx.x * 8 + warp;
    int h = (int)(gw & 7);
    long long bl = gw >> 3;
    long long b = bl >> 12;
    const float* Pl = P + bl * 384;
    const float* Vb = P + b * (long long)NL * 384;
    float rbx = rb[bl * 2 + 0];
    float rby = rb[bl * 2 + 1];

    float lg[4];
    float mx = -1e30f;
#pragma unroll
    for (int pp = 0; pp < 4; pp++) { lg[pp] = Pl[320 + h * 4 + pp]; mx = fmaxf(mx, lg[pp]); }
    float s = 0.f;
#pragma unroll
    for (int pp = 0; pp < 4; pp++) { lg[pp] = expf(lg[pp] - mx); s += lg[pp]; }
    float inv = 1.f / s;

    int hoff = h * 32 + lane;
    float acc = 0.f;
#pragma unroll
    for (int pp = 0; pp < 4; pp++) {
        float ox = Pl[256 + h * 8 + pp * 2 + 0];
        float oy = Pl[256 + h * 8 + pp * 2 + 1];
        float gx = (rbx + ox * (1.f / 64.f)) * 64.f - 0.5f;
        float gy = (rby + oy * (1.f / 64.f)) * 64.f - 0.5f;
        float x0f = floorf(gx), y0f = floorf(gy);
        int x0 = (int)x0f, y0 = (int)y0f;
        float wx1 = gx - x0f, wy1 = gy - y0f;
        float wx0 = 1.f - wx1, wy0 = 1.f - wy1;

        float v00 = 0.f, v10 = 0.f, v01 = 0.f, v11 = 0.f;
        if ((unsigned)x0       < 64u && (unsigned)y0       < 64u) v00 = Vb[(long long)(y0 * 64 + x0) * 384 + hoff];
        if ((unsigned)(x0 + 1) < 64u && (unsigned)y0       < 64u) v10 = Vb[(long long)(y0 * 64 + x0 + 1) * 384 + hoff];
        if ((unsigned)x0       < 64u && (unsigned)(y0 + 1) < 64u) v01 = Vb[(long long)((y0 + 1) * 64 + x0) * 384 + hoff];
        if ((unsigned)(x0 + 1) < 64u && (unsigned)(y0 + 1) < 64u) v11 = Vb[(long long)((y0 + 1) * 64 + x0 + 1) * 384 + hoff];

        float sv = v00 * (wx0 * wy0) + v10 * (wx1 * wy0) + v01 * (wx0 * wy1) + v11 * (wx1 * wy1);
        acc = fmaf(lg[pp] * inv, sv, acc);
    }
    __nv_bfloat16 hv = __float2bfloat16(acc);
    __nv_bfloat16 lv = __float2bfloat16(acc - __bfloat162float(hv));
    size_t idx = (size_t)bl * 256 + hoff;
    g_sdT_hi[idx] = hv;
    g_sdT_lo[idx] = lv;
}

// ================= launch =================
extern "C" void kernel_launch(void* const* d_in, const int* in_sizes, int n_in,
                              void* d_out, int out_size)
{
    const float* x       = (const float*)d_in[0];
    const float* rb      = (const float*)d_in[1];
    const float* cv1_w   = (const float*)d_in[3];
    const float* m0c1    = (const float*)d_in[4];
    const float* m0c2    = (const float*)d_in[5];
    const float* m1c1    = (const float*)d_in[6];
    const float* m1c2    = (const float*)d_in[7];
    const float* vproj_w = (const float*)d_in[8];
    const float* vproj_b = (const float*)d_in[9];
    const float* off_w   = (const float*)d_in[10];
    const float* off_b   = (const float*)d_in[11];
    const float* aw_w    = (const float*)d_in[12];
    const float* aw_b    = (const float*)d_in[13];
    const float* out_w   = (const float*)d_in[14];
    const float* out_b   = (const float*)d_in[15];
    const float* cv2_w   = (const float*)d_in[16];
    float* out = (float*)d_out;

    __nv_bfloat16 *xT_h, *xT_l, *catT_h, *catT_l, *tmpT_h, *tmpT_l, *sdT_h, *sdT_l;
    float *P, *bias384, *biasF;
    uint8_t *Wcv1, *Wc, *Wproj, *Wcv2;
    cudaGetSymbolAddress((void**)&xT_h,   g_xT_hi);
    cudaGetSymbolAddress((void**)&xT_l,   g_xT_lo);
    cudaGetSymbolAddress((void**)&catT_h, g_catT_hi);
    cudaGetSymbolAddress((void**)&catT_l, g_catT_lo);
    cudaGetSymbolAddress((void**)&tmpT_h, g_tmpT_hi);
    cudaGetSymbolAddress((void**)&tmpT_l, g_tmpT_lo);
    cudaGetSymbolAddress((void**)&sdT_h,  g_sdT_hi);
    cudaGetSymbolAddress((void**)&sdT_l,  g_sdT_lo);
    cudaGetSymbolAddress((void**)&P,      g_P);
    cudaGetSymbolAddress((void**)&bias384,g_bias384);
    cudaGetSymbolAddress((void**)&biasF,  g_biasF);
    cudaGetSymbolAddress((void**)&Wcv1,   g_Wcv1);
    cudaGetSymbolAddress((void**)&Wc,     g_Wc);
    cudaGetSymbolAddress((void**)&Wproj,  g_Wproj);
    cudaGetSymbolAddress((void**)&Wcv2,   g_Wcv2);

    const int SMEM128 = 2 * 65536 + 1024;
    const int SMEM64  = 2 * 49152 + 1024;
    cudaFuncSetAttribute(gemm_tc<128>, cudaFuncAttributeMaxDynamicSharedMemorySize, SMEM128);
    cudaFuncSetAttribute(gemm_tc<64>,  cudaFuncAttributeMaxDynamicSharedMemorySize, SMEM64);

    const size_t WCS = 4ull * 36 * 16384;   // per-conv weight bytes (NT=64 layout)
    const int BIG = 1 << 30;

    // ---- prep (merged) ----
    prep_all<<<29122, 256>>>(cv1_w, m0c1, m0c2, m1c1, m1c2,
                             vproj_w, vproj_b, off_w, off_b, aw_w, aw_b,
                             out_w, cv2_w, x);
    prep_fold<<<512, 256>>>(cv2_w, out_b);

    // ---- cv1: xT[512] -> catT[0:512) (SiLU) ----
    gemm_tc<128><<<dim3(4, 32, NB), 256, SMEM128>>>(xT_h, xT_l, 512, 0,
        nullptr, nullptr, 0, BIG, Wcv1, 8, 0,
        nullptr, catT_h, catT_l, CCAT, 0, nullptr, 0, 1);
    // ---- conv0: catT b[256:512) -> tmpT (SiLU) ----
    gemm_tc<64><<<dim3(4, 32, NB), 256, SMEM64>>>(catT_h, catT_l, CCAT, 256,
        nullptr, nullptr, 0, BIG, Wc + 0 * WCS, 36, 1,
        nullptr, tmpT_h, tmpT_l, 256, 0, nullptr, 0, 1);
    // ---- conv1: tmpT -> catT b1[512:768) (SiLU) ----
    gemm_tc<64><<<dim3(4, 32, NB), 256, SMEM64>>>(tmpT_h, tmpT_l, 256, 0,
        nullptr, nullptr, 0, BIG, Wc + 1 * WCS, 36, 1,
        nullptr, catT_h, catT_l, CCAT, 512, nullptr, 0, 1);
    // ---- conv2: catT b1 -> tmpT (SiLU) ----
    gemm_tc<64><<<dim3(4, 32, NB), 256, SMEM64>>>(catT_h, catT_l, CCAT, 512,
        nullptr, nullptr, 0, BIG, Wc + 2 * WCS, 36, 1,
        nullptr, tmpT_h, tmpT_l, 256, 0, nullptr, 0, 1);
    // ---- conv3: tmpT -> catT b2[768:1024) (SiLU) ----
    gemm_tc<64><<<dim3(4, 32, NB), 256, SMEM64>>>(tmpT_h, tmpT_l, 256, 0,
        nullptr, nullptr, 0, BIG, Wc + 3 * WCS, 36, 1,
        nullptr, catT_h, catT_l, CCAT, 768, nullptr, 0, 1);
    // ---- proj: catT b2 -> P[b][p][384] (+bias) ----
    gemm_tc<128><<<dim3(3, 32, NB), 256, SMEM128>>>(catT_h, catT_l, CCAT, 768,
        nullptr, nullptr, 0, BIG, Wproj, 4, 0,
        P, nullptr, nullptr, 0, 0, bias384, 1, 0);
    // ---- deformable sampling -> sdT hi/lo ----
    msda_kernel<<<32768, 256>>>(P, rb);
    // ---- cv2 (out-proj folded): K = catT[0:1024) ++ sdT[0:256) -> out fp32 NCHW (SiLU) ----
    gemm_tc<128><<<dim3(4, 32, NB), 256, SMEM128>>>(catT_h, catT_l, CCAT, 0,
        sdT_h, sdT_l, 256, 16, Wcv2, 20, 0,
        out, nullptr, nullptr, 0, 0, biasF, 2, 1);
}

// round 14
// speedup vs baseline: 1.2516x; 1.0357x over previous
#include <cuda_runtime.h>
#include <cuda_bf16.h>
#include <stdint.h>
#include <math.h>

#define NB 8
#define NL 4096
#define CCAT 1152   // padded concat channel stride (1024 used)

// ================= scratch (device globals) =================
__device__ __align__(1024) __nv_bfloat16 g_xT_hi[(size_t)NB * NL * 512];
__device__ __align__(1024) __nv_bfloat16 g_xT_lo[(size_t)NB * NL * 512];
__device__ __align__(1024) __nv_bfloat16 g_catT_hi[(size_t)NB * NL * CCAT];
__device__ __align__(1024) __nv_bfloat16 g_catT_lo[(size_t)NB * NL * CCAT];
__device__ __align__(1024) __nv_bfloat16 g_tmpT_hi[(size_t)NB * NL * 256];
__device__ __align__(1024) __nv_bfloat16 g_tmpT_lo[(size_t)NB * NL * 256];
__device__ __align__(1024) __nv_bfloat16 g_sdT_hi[(size_t)NB * NL * 256];
__device__ __align__(1024) __nv_bfloat16 g_sdT_lo[(size_t)NB * NL * 256];
__device__ __align__(1024) float g_P[(size_t)NB * NL * 384];   // 256 val | 64 off | 32 aw | 32 pad
__device__ float g_bias384[384];
__device__ float g_biasF[512];                                  // folded cv2 bias
__device__ __align__(1024) float g_outwT[256 * 256];            // out_w transposed [c][d]

// Pre-swizzled weight tiles, ALL NT=64: [n_tile][stage][ hi 8KB | lo 8KB ]
// row r at r*128 + (kbyte ^ ((r&7)*16))  (ldmatrix-ready)
__device__ __align__(1024) uint8_t g_Wcv1 [8  * 8  * 16384];   // 512 co, K=512
__device__ __align__(1024) uint8_t g_Wc   [4][4 * 36 * 16384]; // 256 co, K=2304
__device__ __align__(1024) uint8_t g_Wproj[6  * 4  * 16384];   // 384 co, K=256
__device__ __align__(1024) uint8_t g_Wcv2 [8  * 20 * 16384];   // 512 co, K=1280 (last 256 = folded)

__device__ __forceinline__ float silu_f(float x) { return x / (1.0f + expf(-x)); }

// ================= PTX helpers (compute_103-safe) =================
__device__ __forceinline__ uint32_t smem_u32(const void* p) {
    uint32_t a;
    asm("{ .reg .u64 t; cvta.to.shared.u64 t, %1; cvt.u32.u64 %0, t; }" : "=r"(a) : "l"(p));
    return a;
}
#define CP_COMMIT() asm volatile("cp.async.commit_group;" ::: "memory")
#define CP_WAIT(n)  asm volatile("cp.async.wait_group %0;" :: "n"(n) : "memory")

__device__ __forceinline__ void cpa16(uint32_t d, const void* s, int sz) {
    asm volatile("cp.async.cg.shared.global [%0], [%1], 16, %2;"
                 :: "r"(d), "l"(s), "r"(sz) : "memory");
}
__device__ __forceinline__ void ldsm4(uint32_t a, uint32_t* r) {
    asm volatile("ldmatrix.sync.aligned.m8n8.x4.shared.b16 {%0,%1,%2,%3}, [%4];"
                 : "=r"(r[0]), "=r"(r[1]), "=r"(r[2]), "=r"(r[3]) : "r"(a));
}
__device__ __forceinline__ void mma16816(float* d, const uint32_t* a, const uint32_t* b) {
    asm volatile("mma.sync.aligned.m16n8k16.row.col.f32.bf16.bf16.f32 "
                 "{%0,%1,%2,%3}, {%4,%5,%6,%7}, {%8,%9}, {%0,%1,%2,%3};"
                 : "+f"(d[0]), "+f"(d[1]), "+f"(d[2]), "+f"(d[3])
                 : "r"(a[0]), "r"(a[1]), "r"(a[2]), "r"(a[3]), "r"(b[0]), "r"(b[1]));
}

// ================= weight store (NT=64 tiles) =================
__device__ __forceinline__ void wstore64(uint8_t* dst, int n_stages, int co, int k, float v) {
    int tile = co >> 6, rr = co & 63, st = k >> 6, kk = k & 63;
    __nv_bfloat16 h = __float2bfloat16(v);
    __nv_bfloat16 l = __float2bfloat16(v - __bfloat162float(h));
    size_t base = (size_t)(tile * n_stages + st) * 16384;
    uint32_t off = (uint32_t)(rr * 128 + ((kk * 2) ^ ((rr & 7) * 16)));
    *(__nv_bfloat16*)(dst + base + off) = h;
    *(__nv_bfloat16*)(dst + base + 8192 + off) = l;
}

// ================= merged prep kernel =================
__global__ void prep_all(const float* __restrict__ cv1w,
                         const float* __restrict__ c0w, const float* __restrict__ c1w,
                         const float* __restrict__ c2w, const float* __restrict__ c3w,
                         const float* __restrict__ vw, const float* __restrict__ vb,
                         const float* __restrict__ ow, const float* __restrict__ ob,
                         const float* __restrict__ aww, const float* __restrict__ awb,
                         const float* __restrict__ outw,
                         const float* __restrict__ cv2w,
                         const float* __restrict__ x)
{
    int bid = blockIdx.x, tid = threadIdx.x;
    if (bid < 1024) {                                    // cv1
        int i = bid * 256 + tid;
        int co = i >> 9, k = i & 511;
        wstore64(g_Wcv1, 8, co, k, cv1w[co * 512 + k]);
    } else if (bid < 10240) {                            // convs
        int seg = (bid - 1024) / 2304;
        int i = ((bid - 1024) - seg * 2304) * 256 + tid;
        int co = i / 2304, k = i - co * 2304;
        int tap = k >> 8, ci = k & 255;
        const float* w = (seg == 0) ? c0w : (seg == 1) ? c1w : (seg == 2) ? c2w : c3w;
        wstore64(&g_Wc[seg][0], 36, co, k, w[(co * 256 + ci) * 9 + tap]);
    } else if (bid < 10624) {                            // proj
        int i = (bid - 10240) * 256 + tid;
        int co = i >> 8, k = i & 255;
        float v = (co < 256) ? vw[k * 256 + co]
                : (co < 320) ? ow[k * 64 + (co - 256)]
                : (co < 352) ? aww[k * 32 + (co - 320)] : 0.f;
        wstore64(g_Wproj, 4, co, k, v);
    } else if (bid < 10626) {                            // bias384
        int j = (bid - 10624) * 256 + tid;
        if (j < 384)
            g_bias384[j] = (j < 256) ? vb[j] : (j < 320) ? ob[j - 256] : (j < 352) ? awb[j - 320] : 0.f;
    } else if (bid < 12674) {                            // cv2 first 1024 K
        int i = (bid - 10626) * 256 + tid;
        int co = i >> 10, k = i & 1023;
        wstore64(g_Wcv2, 20, co, k, cv2w[co * 1280 + k]);
    } else if (bid < 12738) {                            // transpose out_w
        __shared__ float t[32][33];
        int bb = bid - 12674;
        int bx = bb & 7, by = bb >> 3;
        int tx = tid & 31, ty = tid >> 5;
#pragma unroll
        for (int i = 0; i < 4; i++)
            t[ty + i * 8][tx] = outw[(by * 32 + ty + i * 8) * 256 + bx * 32 + tx];
        __syncthreads();
#pragma unroll
        for (int i = 0; i < 4; i++)
            g_outwT[(bx * 32 + ty + i * 8) * 256 + by * 32 + tx] = t[tx][ty + i * 8];
    } else {                                             // xT transpose + split
        __shared__ float t[32][33];
        int idx = bid - 12738;
        int b = idx >> 11;
        int rem = idx & 2047;
        int p0 = (rem & 127) * 32, c0 = (rem >> 7) * 32;
        int tx = tid & 31, ty = tid >> 5;
        const float* xb = x + (size_t)b * 512 * 4096;
#pragma unroll
        for (int i = 0; i < 4; i++)
            t[ty + i * 8][tx] = xb[(size_t)(c0 + ty + i * 8) * 4096 + p0 + tx];
        __syncthreads();
#pragma unroll
        for (int i = 0; i < 4; i++) {
            int pp = p0 + ty + i * 8, cc = c0 + tx;
            float v = t[tx][ty + i * 8];
            __nv_bfloat16 h = __float2bfloat16(v);
            __nv_bfloat16 l = __float2bfloat16(v - __bfloat162float(h));
            size_t idx2 = ((size_t)b * 4096 + pp) * 512 + cc;
            g_xT_hi[idx2] = h;
            g_xT_lo[idx2] = l;
        }
    }
}

// Fold out-projection into cv2 (reads g_outwT coalesced); also folds bias.
__global__ void prep_fold(const float* __restrict__ cv2w, const float* __restrict__ outb) {
    __shared__ float srow[256];
    __shared__ float red[256];
    int o = blockIdx.x, d = threadIdx.x;
    float sv = cv2w[o * 1280 + 1024 + d];
    srow[d] = sv;
    red[d] = sv * outb[d];
    __syncthreads();
    float acc = 0.f;
#pragma unroll 4
    for (int c = 0; c < 256; c++) acc = fmaf(srow[c], g_outwT[c * 256 + d], acc);
    wstore64(g_Wcv2, 20, o, 1024 + d, acc);
    for (int st = 128; st > 0; st >>= 1) {
        __syncthreads();
        if (d < st) red[d] += red[d + st];
    }
    if (d == 0) g_biasF[o] = red[0];
}

// ================= tensor-core GEMM (mma.sync bf16, split hi/lo x3, NT=64) =================
// 48KB/stage double-buffered -> 2 CTAs/SM. Stages >= splitS read from A2.
__global__ void __launch_bounds__(256, 2)
gemm_tc(const __nv_bfloat16* __restrict__ A_hi, const __nv_bfloat16* __restrict__ A_lo,
        int Cs, int c0,
        const __nv_bfloat16* __restrict__ A2_hi, const __nv_bfloat16* __restrict__ A2_lo,
        int Cs2, int splitS,
        const uint8_t* __restrict__ W, int n_stages, int conv_mode,
        float* __restrict__ outF,
        __nv_bfloat16* __restrict__ O_hi, __nv_bfloat16* __restrict__ O_lo,
        int CsO, int c0O,
        const float* __restrict__ bias, int out_mode, int act)
{
    constexpr int NG  = 4;                   // n-groups of 8 cols per thread
    constexpr int NBP = 2;                   // B ldmatrix row-pair groups
    constexpr int SBYTES = 32768 + 16384;    // stage bytes (A 32K + B hi/lo 16K)
    extern __shared__ uint8_t dyn[];
    uint8_t* dynp = dyn + ((1024u - (smem_u32(dyn) & 1023u)) & 1023u);
    uint32_t dynb = smem_u32(dynp);

    int tid = threadIdx.x;
    int lane = tid & 31, w = tid >> 5;
    int b = blockIdx.z, n_tile = blockIdx.x;
    int p0 = blockIdx.y * 128;

    const __nv_bfloat16* Ah = A_hi + (size_t)b * NL * Cs + c0;
    const __nv_bfloat16* Al = A_lo + (size_t)b * NL * Cs + c0;
    const __nv_bfloat16* A2h = A2_hi ? A2_hi + (size_t)b * NL * Cs2 : nullptr;
    const __nv_bfloat16* A2l = A2_lo ? A2_lo + (size_t)b * NL * Cs2 : nullptr;
    const uint8_t* Wt = W + (size_t)n_tile * n_stages * 16384;

    // ---- cp.async stage loader (double buffer) ----
    auto issue = [&](int s, int buf) {
        uint32_t bo = dynb + buf * SBYTES;
        const __nv_bfloat16 *ah, *al;
        int cs, ci0, ky = 0, kx = 0;
        if (s >= splitS) {
            ah = A2h; al = A2l; cs = Cs2; ci0 = (s - splitS) * 64;
        } else if (conv_mode) {
            int tap = s >> 2; ky = tap / 3; kx = tap - ky * 3;
            ah = Ah; al = Al; cs = Cs; ci0 = (s & 3) * 64;
        } else {
            ah = Ah; al = Al; cs = Cs; ci0 = s * 64;
        }
#pragma unroll
        for (int t = 0; t < 4; t++) {
            int f = tid + t * 256;                    // 0..1023
            int row = f >> 3, q = f & 7;
            int p = p0 + row;
            int psrc = p, valid = 1;
            if (conv_mode && s < splitS) {
                int yy = (p >> 6) + ky - 1, xx = (p & 63) + kx - 1;
                valid = ((unsigned)yy < 64u) && ((unsigned)xx < 64u);
                psrc = valid ? (p + (ky - 1) * 64 + (kx - 1)) : p;
            }
            uint32_t off = (uint32_t)(row * 128 + ((q * 16) ^ ((row & 7) * 16)));
            int sz = valid ? 16 : 0;
            cpa16(bo + off,         ah + (size_t)psrc * cs + ci0 + q * 8, sz);
            cpa16(bo + 16384 + off, al + (size_t)psrc * cs + ci0 + q * 8, sz);
        }
        const uint8_t* ws = Wt + (size_t)s * 16384;
#pragma unroll
        for (int t = 0; t < 4; t++) {
            int f = tid + t * 256;                    // linear copy of pre-swizzled B image (16KB)
            cpa16(bo + 32768 + f * 16, ws + f * 16, 16);
        }
    };

    // ---- per-lane ldmatrix bases ----
    int lr = lane & 7, g = lane >> 3;
    int m0w = (w & 3) * 32, n0w = (w >> 2) * 32;
    uint32_t xorv = (uint32_t)(lr * 16);
    int kfixA = (g >> 1) * 16;
    int rowA = m0w + (g & 1) * 8 + lr;
    uint32_t aBase[2];
    aBase[0] = dynb + (uint32_t)(rowA * 128);
    aBase[1] = dynb + (uint32_t)((rowA + 16) * 128);
    int kfixB = (g & 1) * 16;
    uint32_t bBase[NBP];
#pragma unroll
    for (int bp = 0; bp < NBP; bp++) {
        int rowB = n0w + bp * 16 + (g >> 1) * 8 + lr;
        bBase[bp] = dynb + 32768u + (uint32_t)(rowB * 128);
    }

    float acc[2][NG][4];
#pragma unroll
    for (int mi = 0; mi < 2; mi++)
#pragma unroll
        for (int ng = 0; ng < NG; ng++)
#pragma unroll
            for (int q = 0; q < 4; q++) acc[mi][ng][q] = 0.f;

    issue(0, 0); CP_COMMIT();

    for (int s = 0; s < n_stages; s++) {
        int buf = s & 1;
        if (s + 1 < n_stages) { issue(s + 1, buf ^ 1); CP_COMMIT(); CP_WAIT(1); }
        else                  { CP_WAIT(0); }
        __syncthreads();

        uint32_t bo = (uint32_t)(buf * SBYTES);
#pragma unroll
        for (int kk8 = 0; kk8 < 4; kk8++) {
            int kb = kk8 * 32;
            uint32_t ka  = (uint32_t)((kb + kfixA) ^ (int)xorv);
            uint32_t kbb = (uint32_t)((kb + kfixB) ^ (int)xorv);
            uint32_t ahf[2][4], alf[2][4];
            ldsm4(aBase[0] + bo + ka,          ahf[0]);
            ldsm4(aBase[1] + bo + ka,          ahf[1]);
            ldsm4(aBase[0] + 16384 + bo + ka,  alf[0]);
            ldsm4(aBase[1] + 16384 + bo + ka,  alf[1]);
            uint32_t bhf[NBP][4], blf[NBP][4];
#pragma unroll
            for (int bp = 0; bp < NBP; bp++) {
                ldsm4(bBase[bp] + bo + kbb,        bhf[bp]);
                ldsm4(bBase[bp] + 8192 + bo + kbb, blf[bp]);
            }
#pragma unroll
            for (int mi = 0; mi < 2; mi++)
#pragma unroll
                for (int ng = 0; ng < NG; ng++) {
                    const uint32_t* bh = &bhf[ng >> 1][(ng & 1) * 2];
                    const uint32_t* bl = &blf[ng >> 1][(ng & 1) * 2];
                    mma16816(acc[mi][ng], ahf[mi], bh);   // hi*hi
                    mma16816(acc[mi][ng], ahf[mi], bl);   // hi*lo
                    mma16816(acc[mi][ng], alf[mi], bh);   // lo*hi
                }
        }
        __syncthreads();
    }

    // ---- epilogue ----
    int prb = p0 + m0w + (lane >> 2);
    int colb = n0w + 2 * (lane & 3);
#pragma unroll
    for (int mi = 0; mi < 2; mi++)
#pragma unroll
        for (int ng = 0; ng < NG; ng++) {
            int cog = n_tile * 64 + colb + ng * 8;
#pragma unroll
            for (int half = 0; half < 2; half++) {
                int pe = prb + mi * 16 + half * 8;
                float v0 = acc[mi][ng][half * 2 + 0];
                float v1 = acc[mi][ng][half * 2 + 1];
                if (out_mode == 0) {
                    if (bias) { v0 += bias[cog]; v1 += bias[cog + 1]; }
                    if (act)  { v0 = silu_f(v0); v1 = silu_f(v1); }
                    __nv_bfloat16 h0 = __float2bfloat16(v0), h1 = __float2bfloat16(v1);
                    __nv_bfloat16 l0 = __float2bfloat16(v0 - __bfloat162float(h0));
                    __nv_bfloat16 l1 = __float2bfloat16(v1 - __bfloat162float(h1));
                    uint32_t hp = (uint32_t)__bfloat16_as_ushort(h0) | ((uint32_t)__bfloat16_as_ushort(h1) << 16);
                    uint32_t lp = (uint32_t)__bfloat16_as_ushort(l0) | ((uint32_t)__bfloat16_as_ushort(l1) << 16);
                    size_t ob = ((size_t)b * NL + pe) * CsO + c0O + cog;
                    *(uint32_t*)(O_hi + ob) = hp;
                    *(uint32_t*)(O_lo + ob) = lp;
                } else if (out_mode == 1) {
                    float2 v;
                    v.x = v0 + bias[cog];
                    v.y = v1 + bias[cog + 1];
                    *(float2*)&outF[((size_t)b * NL + pe) * 384 + cog] = v;
                } else {
                    float b0 = bias ? bias[cog] : 0.f;
                    float b1 = bias ? bias[cog + 1] : 0.f;
                    outF[((size_t)(b * 512 + cog)     << 12) + pe] = silu_f(v0 + b0);
                    outF[((size_t)(b * 512 + cog + 1) << 12) + pe] = silu_f(v1 + b1);
                }
            }
        }
}

// ================= deformable sampling =================
__global__ void msda_kernel(const float* __restrict__ P, const float* __restrict__ rb)
{
    int warp = threadIdx.x >> 5;
    int lane = threadIdx.x & 31;
    long long gw = (long long)blockIdx.x * 8 + warp;
    int h = (int)(gw & 7);
    long long bl = gw >> 3;
    long long b = bl >> 12;
    const float* Pl = P + bl * 384;
    const float* Vb = P + b * (long long)NL * 384;
    float rbx = rb[bl * 2 + 0];
    float rby = rb[bl * 2 + 1];

    float lg[4];
    float mx = -1e30f;
#pragma unroll
    for (int pp = 0; pp < 4; pp++) { lg[pp] = Pl[320 + h * 4 + pp]; mx = fmaxf(mx, lg[pp]); }
    float s = 0.f;
#pragma unroll
    for (int pp = 0; pp < 4; pp++) { lg[pp] = expf(lg[pp] - mx); s += lg[pp]; }
    float inv = 1.f / s;

    int hoff = h * 32 + lane;
    float acc = 0.f;
#pragma unroll
    for (int pp = 0; pp < 4; pp++) {
        float ox = Pl[256 + h * 8 + pp * 2 + 0];
        float oy = Pl[256 + h * 8 + pp * 2 + 1];
        float gx = (rbx + ox * (1.f / 64.f)) * 64.f - 0.5f;
        float gy = (rby + oy * (1.f / 64.f)) * 64.f - 0.5f;
        float x0f = floorf(gx), y0f = floorf(gy);
        int x0 = (int)x0f, y0 = (int)y0f;
        float wx1 = gx - x0f, wy1 = gy - y0f;
        float wx0 = 1.f - wx1, wy0 = 1.f - wy1;

        float v00 = 0.f, v10 = 0.f, v01 = 0.f, v11 = 0.f;
        if ((unsigned)x0       < 64u && (unsigned)y0       < 64u) v00 = Vb[(long long)(y0 * 64 + x0) * 384 + hoff];
        if ((unsigned)(x0 + 1) < 64u && (unsigned)y0       < 64u) v10 = Vb[(long long)(y0 * 64 + x0 + 1) * 384 + hoff];
        if ((unsigned)x0       < 64u && (unsigned)(y0 + 1) < 64u) v01 = Vb[(long long)((y0 + 1) * 64 + x0) * 384 + hoff];
        if ((unsigned)(x0 + 1) < 64u && (unsigned)(y0 + 1) < 64u) v11 = Vb[(long long)((y0 + 1) * 64 + x0 + 1) * 384 + hoff];

        float sv = v00 * (wx0 * wy0) + v10 * (wx1 * wy0) + v01 * (wx0 * wy1) + v11 * (wx1 * wy1);
        acc = fmaf(lg[pp] * inv, sv, acc);
    }
    __nv_bfloat16 hv = __float2bfloat16(acc);
    __nv_bfloat16 lv = __float2bfloat16(acc - __bfloat162float(hv));
    size_t idx = (size_t)bl * 256 + hoff;
    g_sdT_hi[idx] = hv;
    g_sdT_lo[idx] = lv;
}

// ================= launch =================
extern "C" void kernel_launch(void* const* d_in, const int* in_sizes, int n_in,
                              void* d_out, int out_size)
{
    const float* x       = (const float*)d_in[0];
    const float* rb      = (const float*)d_in[1];
    const float* cv1_w   = (const float*)d_in[3];
    const float* m0c1    = (const float*)d_in[4];
    const float* m0c2    = (const float*)d_in[5];
    const float* m1c1    = (const float*)d_in[6];
    const float* m1c2    = (const float*)d_in[7];
    const float* vproj_w = (const float*)d_in[8];
    const float* vproj_b = (const float*)d_in[9];
    const float* off_w   = (const float*)d_in[10];
    const float* off_b   = (const float*)d_in[11];
    const float* aw_w    = (const float*)d_in[12];
    const float* aw_b    = (const float*)d_in[13];
    const float* out_w   = (const float*)d_in[14];
    const float* out_b   = (const float*)d_in[15];
    const float* cv2_w   = (const float*)d_in[16];
    float* out = (float*)d_out;

    __nv_bfloat16 *xT_h, *xT_l, *catT_h, *catT_l, *tmpT_h, *tmpT_l, *sdT_h, *sdT_l;
    float *P, *bias384, *biasF;
    uint8_t *Wcv1, *Wc, *Wproj, *Wcv2;
    cudaGetSymbolAddress((void**)&xT_h,   g_xT_hi);
    cudaGetSymbolAddress((void**)&xT_l,   g_xT_lo);
    cudaGetSymbolAddress((void**)&catT_h, g_catT_hi);
    cudaGetSymbolAddress((void**)&catT_l, g_catT_lo);
    cudaGetSymbolAddress((void**)&tmpT_h, g_tmpT_hi);
    cudaGetSymbolAddress((void**)&tmpT_l, g_tmpT_lo);
    cudaGetSymbolAddress((void**)&sdT_h,  g_sdT_hi);
    cudaGetSymbolAddress((void**)&sdT_l,  g_sdT_lo);
    cudaGetSymbolAddress((void**)&P,      g_P);
    cudaGetSymbolAddress((void**)&bias384,g_bias384);
    cudaGetSymbolAddress((void**)&biasF,  g_biasF);
    cudaGetSymbolAddress((void**)&Wcv1,   g_Wcv1);
    cudaGetSymbolAddress((void**)&Wc,     g_Wc);
    cudaGetSymbolAddress((void**)&Wproj,  g_Wproj);
    cudaGetSymbolAddress((void**)&Wcv2,   g_Wcv2);

    const int SMEM64 = 2 * 49152 + 1024;
    cudaFuncSetAttribute(gemm_tc, cudaFuncAttributeMaxDynamicSharedMemorySize, SMEM64);

    const size_t WCS = 4ull * 36 * 16384;   // per-conv weight bytes
    const int BIG = 1 << 30;

    // ---- prep (merged) ----
    prep_all<<<29122, 256>>>(cv1_w, m0c1, m0c2, m1c1, m1c2,
                             vproj_w, vproj_b, off_w, off_b, aw_w, aw_b,
                             out_w, cv2_w, x);
    prep_fold<<<512, 256>>>(cv2_w, out_b);

    // ---- cv1: xT[512] -> catT[0:512) (SiLU) ----
    gemm_tc<<<dim3(8, 32, NB), 256, SMEM64>>>(xT_h, xT_l, 512, 0,
        nullptr, nullptr, 0, BIG, Wcv1, 8, 0,
        nullptr, catT_h, catT_l, CCAT, 0, nullptr, 0, 1);
    // ---- conv0: catT b[256:512) -> tmpT (SiLU) ----
    gemm_tc<<<dim3(4, 32, NB), 256, SMEM64>>>(catT_h, catT_l, CCAT, 256,
        nullptr, nullptr, 0, BIG, Wc + 0 * WCS, 36, 1,
        nullptr, tmpT_h, tmpT_l, 256, 0, nullptr, 0, 1);
    // ---- conv1: tmpT -> catT b1[512:768) (SiLU) ----
    gemm_tc<<<dim3(4, 32, NB), 256, SMEM64>>>(tmpT_h, tmpT_l, 256, 0,
        nullptr, nullptr, 0, BIG, Wc + 1 * WCS, 36, 1,
        nullptr, catT_h, catT_l, CCAT, 512, nullptr, 0, 1);
    // ---- conv2: catT b1 -> tmpT (SiLU) ----
    gemm_tc<<<dim3(4, 32, NB), 256, SMEM64>>>(catT_h, catT_l, CCAT, 512,
        nullptr, nullptr, 0, BIG, Wc + 2 * WCS, 36, 1,
        nullptr, tmpT_h, tmpT_l, 256, 0, nullptr, 0, 1);
    // ---- conv3: tmpT -> catT b2[768:1024) (SiLU) ----
    gemm_tc<<<dim3(4, 32, NB), 256, SMEM64>>>(tmpT_h, tmpT_l, 256, 0,
        nullptr, nullptr, 0, BIG, Wc + 3 * WCS, 36, 1,
        nullptr, catT_h, catT_l, CCAT, 768, nullptr, 0, 1);
    // ---- proj: catT b2 -> P[b][p][384] (+bias) ----
    gemm_tc<<<dim3(6, 32, NB), 256, SMEM64>>>(catT_h, catT_l, CCAT, 768,
        nullptr, nullptr, 0, BIG, Wproj, 4, 0,
        P, nullptr, nullptr, 0, 0, bias384, 1, 0);
    // ---- deformable sampling -> sdT hi/lo ----
    msda_kernel<<<32768, 256>>>(P, rb);
    // ---- cv2 (out-proj folded): K = catT[0:1024) ++ sdT[0:256) -> out fp32 NCHW (SiLU) ----
    gemm_tc<<<dim3(8, 32, NB), 256, SMEM64>>>(catT_h, catT_l, CCAT, 0,
        sdT_h, sdT_l, 256, 16, Wcv2, 20, 0,
        out, nullptr, nullptr, 0, 0, biasF, 2, 1);
}